// round 2
// baseline (speedup 1.0000x reference)
#include <cuda_runtime.h>
#include <math.h>

// ---------------- problem constants ----------------
#define BB     32
#define CC     64
#define FHH    80
#define FWW    200
#define SPP    36
#define LANES_ 64
#define PE_    78
#define RH_    10
#define RW_    25
#define NPOOL  250
#define KDIM   2304          // SPP * CC   (k = s*64 + c)
#define NROW   2048          // B * LANES
#define NSPLIT 24
#define KSPL   96            // KDIM / NSPLIT

// ---------------- device scratch ----------------
__device__ float g_xf[BB * CC * NPOOL];            // pooled features [b][c][r]
__device__ float g_W2[CC * KDIM];                  // fused conv1d+fc weight [o][s*64+c]
__device__ float g_b2[CC];
__device__ float g_roi[(size_t)NROW * KDIM];       // [n][s*64+c]
__device__ float g_xp_part[NSPLIT][NROW * CC];
__device__ float g_xp[NROW * CC];
__device__ float g_gv[BB * LANES_ * CC];
__device__ unsigned int g_xidx[BB * SPP * LANES_]; // packed xf | xc<<16

// ---------------- K0: precompute per-(b,sp,lane) x indices ----------------
__global__ void xprep_kernel(const float* __restrict__ prior) {
    int idx = blockIdx.x * 256 + threadIdx.x;
    if (idx >= BB * SPP * LANES_) return;
    int b = idx / (SPP * LANES_);
    int rem = idx % (SPP * LANES_);
    int sp = rem / LANES_;
    int lane = rem % LANES_;
    float xv = prior[(b * LANES_ + lane) * PE_ + 6 + 2 * sp] * 0.25f;
    xv = fminf(xv, 199.0f);
    unsigned int xf = (unsigned int)(int)floorf(xv);
    unsigned int xc = (unsigned int)(int)ceilf(xv);
    g_xidx[idx] = xf | (xc << 16);
}

// ---------------- K1: fused streaming pool + ROI gather ----------------
// block = (cg, b): 8 channels, sweep rows y=79..0 through a 4-row ring.
__global__ void fused_pool_gather_kernel(const float* __restrict__ f) {
    int cg = blockIdx.x;     // 0..7 (8 channels each)
    int b  = blockIdx.y;     // 0..31
    int tid = threadIdx.x;

    __shared__ float ring[4 * 8 * FWW];      // [slot][c][x]
    __shared__ float rowsum[8 * FWW];        // [c][x]
    __shared__ unsigned int xidx_s[SPP * LANES_];
    __shared__ int sp_of_y[FHH];
    __shared__ int yc_of_y[FHH];

    // preload x indices for this batch
    for (int i = tid; i < SPP * LANES_; i += 256)
        xidx_s[i] = g_xidx[b * (SPP * LANES_) + i];
    for (int i = tid; i < FHH; i += 256) sp_of_y[i] = -1;
    for (int i = tid; i < 8 * FWW; i += 256) rowsum[i] = 0.f;
    __syncthreads();
    if (tid < SPP) {
        float yv = 0.25f * (319.0f - (320.0f / 71.0f) * (float)(2 * tid));
        yv = fminf(yv, 79.0f);
        int yf = (int)floorf(yv);
        int yc = (int)ceilf(yv);
        sp_of_y[yf] = tid;
        yc_of_y[yf] = yc;
    }
    __syncthreads();

    const float* fb = f + (size_t)(b * CC + cg * 8) * (FHH * FWW);

    for (int y = FHH - 1; y >= 0; y--) {
        int slot = y & 3;
        // load row y: 8 ch x 200 = 400 float4
        {
            const float4* src = (const float4*)fb;
            float4* dst = (float4*)&ring[slot * (8 * FWW)];
            for (int i = tid; i < 400; i += 256) {
                int c = i / 50, x4 = i % 50;
                dst[c * 50 + x4] = src[(c * (FHH * FWW) + y * FWW) / 4 + x4];
            }
        }
        __syncthreads();

        // pool accumulate (thread-local mapping, no sync needed)
        {
            float4* rs = (float4*)rowsum;
            const float4* rw = (const float4*)&ring[slot * (8 * FWW)];
            for (int i = tid; i < 400; i += 256) {
                float4 a = rs[i], bv = rw[i];
                a.x += bv.x; a.y += bv.y; a.z += bv.z; a.w += bv.w;
                rs[i] = a;
            }
        }

        // gather for the sp whose yf == y
        int sp = sp_of_y[y];
        if (sp >= 0) {
            int yc = yc_of_y[y];
            const float* rA = &ring[slot * (8 * FWW)];
            const float* rB = &ring[(yc & 3) * (8 * FWW)];
            for (int i = tid; i < 8 * LANES_; i += 256) {
                int lane = i >> 3, c = i & 7;
                unsigned int p = xidx_s[sp * LANES_ + lane];
                int xf = (int)(p & 0xffffu), xc = (int)(p >> 16);
                float v = rA[c * FWW + xf] + rA[c * FWW + xc] +
                          rB[c * FWW + xf] + rB[c * FWW + xc];
                g_roi[(size_t)(b * LANES_ + lane) * KDIM + sp * CC + cg * 8 + c] =
                    0.25f * v;
            }
        }

        // pool group complete?
        if ((y & 7) == 0) {
            __syncthreads();   // rowsum complete
            int rh = y >> 3;
            // 200 reducer threads; each reads+resets its 8 entries
            if (tid < 8 * RW_) {
                int c = tid / RW_, xq = tid % RW_;
                float s = 0.f;
                #pragma unroll
                for (int q = 0; q < 8; q++) {
                    s += rowsum[c * FWW + xq * 8 + q];
                    rowsum[c * FWW + xq * 8 + q] = 0.f;
                }
                g_xf[(size_t)(b * CC + cg * 8 + c) * NPOOL + rh * RW_ + xq] =
                    s * (1.0f / 64.0f);
            }
        }
        __syncthreads();  // ring slot reuse + rowsum reset ordering
    }
}

// ---------------- K2: fuse conv1d + fc into W2 / b2 ----------------
__global__ void w2_kernel(const float* __restrict__ conv_w,
                          const float* __restrict__ conv_b,
                          const float* __restrict__ fc_w,
                          const float* __restrict__ fc_b) {
    int o = blockIdx.x;      // 0..63
    int q = blockIdx.y;      // 0..3 (c1 group of 16)
    int tid = threadIdx.x;
    __shared__ float fcrow[2048];
    __shared__ float convs[64 * 16 * 5];     // [c2][c1l][k]
    __shared__ float bpart[64];

    for (int i = tid; i < 2048; i += 256) fcrow[i] = fc_w[o * 2048 + i];
    for (int i = tid; i < 5120; i += 256) {
        int c2 = i / 80, rem = i % 80;
        int c1l = rem / 5, k = rem % 5;
        convs[i] = conv_w[(c2 * CC + q * 16 + c1l) * 5 + k];
    }
    __syncthreads();

    for (int i = tid; i < 16 * SPP; i += 256) {
        int c1l = i / SPP, s = i % SPP;
        float acc = 0.f;
        for (int c2 = 0; c2 < CC; c2++) {
            const float* w5 = &convs[c2 * 80 + c1l * 5];
            const float* fr = &fcrow[c2 * 32];
            #pragma unroll
            for (int k = 0; k < 5; k++) {
                int p = s - k;
                if (p >= 0 && p < 32) acc += w5[k] * fr[p];
            }
        }
        g_W2[o * KDIM + s * CC + q * 16 + c1l] = acc;
    }

    if (q == 0) {
        if (tid < CC) {
            float s = 0.f;
            #pragma unroll
            for (int p = 0; p < 32; p++) s += fcrow[tid * 32 + p];
            bpart[tid] = s * conv_b[tid];
        }
        __syncthreads();
        if (tid == 0) {
            float s = fc_b[o];
            for (int j = 0; j < CC; j++) s += bpart[j];
            g_b2[o] = s;
        }
    }
}

// ---------------- K4: Xp_part = ROI(2048x2304) @ W2^T, K-split ----------------
__global__ void gemm_kernel() {
    int mblk = blockIdx.x;               // 0..15, 128 rows
    int spl  = blockIdx.y;               // 0..23, 96 K each
    int tid = threadIdx.x;
    int tx = tid & 15;                   // 4 cols
    int ty = tid >> 4;                   // 8 rows
    int row0 = mblk * 128;
    int k0 = spl * KSPL;

    __shared__ float As[128][36];        // stride 144B (16B aligned)
    __shared__ float Bs[64][36];

    float acc[8][4];
    #pragma unroll
    for (int i = 0; i < 8; i++)
        #pragma unroll
        for (int j = 0; j < 4; j++) acc[i][j] = 0.f;

    for (int kk = 0; kk < KSPL; kk += 32) {
        // load A chunk: 128x32 = 1024 float4
        {
            const float4* src = (const float4*)g_roi;
            for (int it = 0; it < 4; it++) {
                int idx = tid + it * 256;
                int r = idx >> 3, qv = idx & 7;
                float4 v = src[(size_t)(row0 + r) * (KDIM / 4) + (k0 + kk) / 4 + qv];
                *(float4*)&As[r][qv * 4] = v;
            }
        }
        // load B chunk: 64x32 = 512 float4
        {
            const float4* src = (const float4*)g_W2;
            for (int it = 0; it < 2; it++) {
                int idx = tid + it * 256;
                int r = idx >> 3, qv = idx & 7;
                float4 v = src[(size_t)r * (KDIM / 4) + (k0 + kk) / 4 + qv];
                *(float4*)&Bs[r][qv * 4] = v;
            }
        }
        __syncthreads();
        #pragma unroll
        for (int k4 = 0; k4 < 8; k4++) {
            float4 bv[4];
            #pragma unroll
            for (int j = 0; j < 4; j++)
                bv[j] = *(const float4*)&Bs[tx * 4 + j][k4 * 4];
            #pragma unroll
            for (int i = 0; i < 8; i++) {
                float4 a = *(const float4*)&As[ty * 8 + i][k4 * 4];
                #pragma unroll
                for (int j = 0; j < 4; j++) {
                    acc[i][j] += a.x * bv[j].x;
                    acc[i][j] += a.y * bv[j].y;
                    acc[i][j] += a.z * bv[j].z;
                    acc[i][j] += a.w * bv[j].w;
                }
            }
        }
        __syncthreads();
    }
    #pragma unroll
    for (int i = 0; i < 8; i++)
        #pragma unroll
        for (int j = 0; j < 4; j++)
            g_xp_part[spl][(row0 + ty * 8 + i) * CC + tx * 4 + j] = acc[i][j];
}

// ---------------- K4b: reduce split partials + bias ----------------
__global__ void reduce_xp_kernel() {
    int idx = blockIdx.x * 256 + threadIdx.x;
    if (idx >= NROW * CC) return;
    int o = idx & 63;
    float s = g_b2[o];
    #pragma unroll
    for (int sp_ = 0; sp_ < NSPLIT; sp_++) s += g_xp_part[sp_][idx];
    g_xp[idx] = s;
}

// ---------------- K5: attention ----------------
__global__ void attn_kernel() {
    extern __shared__ float sm[];
    float* xfs = sm;                      // [64][251]
    float* xps = sm + 64 * 251;           // [16][64]
    float* wbf = xps + 16 * 64;           // [16][250]

    int lq = blockIdx.x;
    int b = blockIdx.y;
    int tid = threadIdx.x;
    int w = tid >> 5, t = tid & 31;
    int lane = lq * 16 + w;
    int n = b * LANES_ + lane;

    for (int i = tid; i < CC * NPOOL; i += 512) {
        int c = i / NPOOL, r = i % NPOOL;
        xfs[c * 251 + r] = g_xf[(b * CC + c) * NPOOL + r];
    }
    for (int o = t; o < CC; o += 32)
        xps[w * CC + o] = g_xp[n * CC + o];
    __syncthreads();

    float sc[8];
    float mx = -1e30f;
    #pragma unroll
    for (int j = 0; j < 8; j++) {
        int r = t + 32 * j;
        if (r < NPOOL) {
            float s = 0.f;
            #pragma unroll 8
            for (int c = 0; c < CC; c++) s += xps[w * CC + c] * xfs[c * 251 + r];
            s *= 0.125f;
            sc[j] = s;
            mx = fmaxf(mx, s);
        } else sc[j] = -1e30f;
    }
    #pragma unroll
    for (int off = 16; off > 0; off >>= 1)
        mx = fmaxf(mx, __shfl_xor_sync(0xffffffffu, mx, off));
    float sum = 0.f;
    #pragma unroll
    for (int j = 0; j < 8; j++) { sc[j] = __expf(sc[j] - mx); sum += sc[j]; }
    #pragma unroll
    for (int off = 16; off > 0; off >>= 1)
        sum += __shfl_xor_sync(0xffffffffu, sum, off);
    float inv = 1.0f / sum;
    #pragma unroll
    for (int j = 0; j < 8; j++) {
        int r = t + 32 * j;
        if (r < NPOOL) wbf[w * NPOOL + r] = sc[j] * inv;
    }
    __syncwarp();

    for (int c = t; c < CC; c += 32) {
        float s = 0.f;
        #pragma unroll 10
        for (int r = 0; r < NPOOL; r++) s += wbf[w * NPOOL + r] * xfs[c * 251 + r];
        g_gv[b * (LANES_ * CC) + lane * CC + c] = s;
    }
}

// ---------------- K6: conv1x1 + relu + broadcast-add prior ----------------
__global__ void final_kernel(const float* __restrict__ w1x1,
                             const float* __restrict__ b1x1,
                             const float* __restrict__ prior,
                             float* __restrict__ out) {
    int og = blockIdx.x;
    int b = blockIdx.y;
    int tid = threadIdx.x;
    int w = tid >> 5, t = tid & 31;

    __shared__ float gvs[4096];
    __shared__ float vals[8];
    for (int i = tid; i < 4096; i += 256) gvs[i] = g_gv[b * 4096 + i];
    __syncthreads();

    int o = og * 8 + w;
    const float* wrow = w1x1 + (size_t)o * 4096;
    float s = 0.f;
    for (int j = t * 4; j < 4096; j += 128) {
        float4 wv = *(const float4*)&wrow[j];
        float4 gv = *(const float4*)&gvs[j];
        s += wv.x * gv.x + wv.y * gv.y + wv.z * gv.z + wv.w * gv.w;
    }
    #pragma unroll
    for (int off = 16; off > 0; off >>= 1)
        s += __shfl_xor_sync(0xffffffffu, s, off);
    if (t == 0) vals[w] = fmaxf(s + b1x1[o], 0.f);
    __syncthreads();

    for (int i = tid; i < 8 * PE_; i += 256) {
        int oo = i / PE_, e = i % PE_;
        int oabs = og * 8 + oo;
        int idx = b * (CC * PE_) + oabs * PE_ + e;
        out[idx] = vals[oo] + prior[idx];
    }
}

// ---------------- launch ----------------
extern "C" void kernel_launch(void* const* d_in, const int* in_sizes, int n_in,
                              void* d_out, int out_size) {
    const float* feat    = (const float*)d_in[0];
    const float* prior   = (const float*)d_in[1];
    const float* conv_w  = (const float*)d_in[2];
    const float* conv_b  = (const float*)d_in[3];
    const float* fc_w    = (const float*)d_in[4];
    const float* fc_b    = (const float*)d_in[5];
    const float* w1x1    = (const float*)d_in[6];
    const float* b1x1    = (const float*)d_in[7];
    float* out = (float*)d_out;

    const int attn_smem = (64 * 251 + 16 * 64 + 16 * 250) * (int)sizeof(float);
    cudaFuncSetAttribute(attn_kernel, cudaFuncAttributeMaxDynamicSharedMemorySize,
                         attn_smem);

    xprep_kernel<<<(BB * SPP * LANES_ + 255) / 256, 256>>>(prior);
    w2_kernel<<<dim3(CC, 4), 256>>>(conv_w, conv_b, fc_w, fc_b);
    fused_pool_gather_kernel<<<dim3(8, BB), 256>>>(feat);
    gemm_kernel<<<dim3(16, NSPLIT), 256>>>();
    reduce_xp_kernel<<<(NROW * CC + 255) / 256, 256>>>();
    attn_kernel<<<dim3(4, BB), 512, attn_smem>>>();
    final_kernel<<<dim3(8, BB), 256>>>(w1x1, b1x1, prior, out);
}

// round 4
// speedup vs baseline: 1.6515x; 1.6515x over previous
#include <cuda_runtime.h>
#include <math.h>

// ---------------- problem constants ----------------
#define BB     32
#define CC     64
#define FHH    80
#define FWW    200
#define SPP    36
#define LANES_ 64
#define PE_    78
#define RH_    10
#define RW_    25
#define NPOOL  250
#define KDIM   2304          // SPP * CC   (k = s*64 + c)
#define NROW   2048          // B * LANES
#define NSPLIT 12
#define KSPL   192           // KDIM / NSPLIT

// ---------------- device scratch ----------------
__device__ float g_xf[BB * CC * NPOOL];             // pooled features [b][c][r]
__device__ float g_W2t[KDIM * CC];                  // fused weight, k-major [k][o]
__device__ float g_b2[CC];
__device__ float g_roiT[(size_t)KDIM * NROW];       // roi, k-major [k][n]
__device__ float g_xp_part[NSPLIT][NROW * CC];
__device__ float g_xp[NROW * CC];
__device__ float g_gv[BB * LANES_ * CC];
__device__ unsigned int g_xidx[BB * SPP * LANES_];  // packed xf | xc<<16

// ---------------- K0: precompute per-(b,sp,lane) x indices ----------------
__global__ void xprep_kernel(const float* __restrict__ prior) {
    int idx = blockIdx.x * 256 + threadIdx.x;
    if (idx >= BB * SPP * LANES_) return;
    int b = idx / (SPP * LANES_);
    int rem = idx % (SPP * LANES_);
    int sp = rem / LANES_;
    int lane = rem % LANES_;
    float xv = prior[(b * LANES_ + lane) * PE_ + 6 + 2 * sp] * 0.25f;
    xv = fminf(xv, 199.0f);
    unsigned int xf = (unsigned int)(int)floorf(xv);
    unsigned int xc = (unsigned int)(int)ceilf(xv);
    g_xidx[idx] = xf | (xc << 16);
}

// ---------------- K1: 8x8 average pool, one thread per output ----------------
__global__ void pool_kernel(const float* __restrict__ f) {
    int idx = blockIdx.x * 256 + threadIdx.x;
    if (idx >= BB * CC * NPOOL) return;
    int bc = idx / NPOOL;
    int r = idx % NPOOL;
    int rh = r / RW_, rw = r % RW_;
    const float* base = f + (size_t)bc * (FHH * FWW) + rh * 8 * FWW + rw * 8;
    float s = 0.f;
    #pragma unroll
    for (int rr = 0; rr < 8; rr++) {
        float4 a = *(const float4*)(base + rr * FWW);
        float4 b = *(const float4*)(base + rr * FWW + 4);
        s += a.x + a.y + a.z + a.w + b.x + b.y + b.z + b.w;
    }
    g_xf[idx] = s * (1.0f / 64.0f);
}

// ---------------- K2: ROI gather via row staging -> g_roiT (k-major) ------
__global__ void gather_kernel(const float* __restrict__ f) {
    int sp = blockIdx.x;                 // 0..35
    int cq = blockIdx.y;                 // 0..3  (16 channels each)
    int b  = blockIdx.z;                 // 0..31
    int tid = threadIdx.x;

    float yv = 0.25f * (319.0f - (320.0f / 71.0f) * (float)(2 * sp));
    yv = fminf(yv, 79.0f);
    int yc = (int)ceilf(yv);
    int yfl = (int)floorf(yv);

    __shared__ float rows[2][16][204];   // [corner(y)][c][x]; 204 keeps rows 16B-aligned
    __shared__ unsigned int xs_s[LANES_];

    if (tid < LANES_)
        xs_s[tid] = g_xidx[(b * SPP + sp) * LANES_ + tid];

    const float* fb = f + (size_t)(b * CC + cq * 16) * (FHH * FWW);
    // 2 rows x 16 ch x 200 = 1600 float4
    for (int i = tid; i < 2 * 16 * 50; i += 256) {
        int j = i / (16 * 50);
        int rem = i % (16 * 50);
        int c = rem / 50;
        int x4 = rem % 50;
        int y = j ? yc : yfl;
        float4 v = *(const float4*)(fb + (size_t)c * (FHH * FWW) + y * FWW + x4 * 4);
        *(float4*)&rows[j][c][x4 * 4] = v;
    }
    __syncthreads();

    // write k-major: g_roiT[(sp*64 + cq*16 + c) * 2048 + b*64 + lane]
    for (int i = tid; i < 16 * LANES_; i += 256) {
        int lane = i & 63;
        int c = i >> 6;
        unsigned int p = xs_s[lane];
        int xf = (int)(p & 0xffffu), xc_ = (int)(p >> 16);
        float v = rows[0][c][xf] + rows[0][c][xc_] +
                  rows[1][c][xf] + rows[1][c][xc_];
        g_roiT[(size_t)(sp * CC + cq * 16 + c) * NROW + b * LANES_ + lane] =
            0.25f * v;
    }
}

// ---------------- K3: fuse conv1d + fc into W2t / b2 ----------------
__global__ void w2_kernel(const float* __restrict__ conv_w,
                          const float* __restrict__ conv_b,
                          const float* __restrict__ fc_w,
                          const float* __restrict__ fc_b) {
    int o = blockIdx.x;      // 0..63
    int q = blockIdx.y;      // 0..3 (c1 group of 16)
    int tid = threadIdx.x;
    __shared__ float fcrow[2048];
    __shared__ float convs[64 * 16 * 5];     // [c2][c1l][k]
    __shared__ float bpart[64];

    for (int i = tid; i < 2048; i += 256) fcrow[i] = fc_w[o * 2048 + i];
    for (int i = tid; i < 5120; i += 256) {
        int c2 = i / 80, rem = i % 80;
        int c1l = rem / 5, k = rem % 5;
        convs[i] = conv_w[(c2 * CC + q * 16 + c1l) * 5 + k];
    }
    __syncthreads();

    for (int i = tid; i < 16 * SPP; i += 256) {
        int c1l = i / SPP, s = i % SPP;
        float acc = 0.f;
        for (int c2 = 0; c2 < CC; c2++) {
            const float* w5 = &convs[c2 * 80 + c1l * 5];
            const float* fr = &fcrow[c2 * 32];
            #pragma unroll
            for (int k = 0; k < 5; k++) {
                int p = s - k;
                if (p >= 0 && p < 32) acc += w5[k] * fr[p];
            }
        }
        g_W2t[(size_t)(s * CC + q * 16 + c1l) * CC + o] = acc;
    }

    if (q == 0) {
        if (tid < CC) {
            float s = 0.f;
            #pragma unroll
            for (int p = 0; p < 32; p++) s += fcrow[tid * 32 + p];
            bpart[tid] = s * conv_b[tid];
        }
        __syncthreads();
        if (tid == 0) {
            float s = fc_b[o];
            for (int j = 0; j < CC; j++) s += bpart[j];
            g_b2[o] = s;
        }
    }
}

// ---------------- K4: Xp_part = ROI^T(k-major) x W2t, K-split --------------
// block: 64 rows x 64 cols, thread tile 4x4, k-major smem (conflict-free).
__global__ void __launch_bounds__(256) gemm_kernel() {
    int mblk = blockIdx.x;               // 0..31, 64 rows each
    int spl  = blockIdx.y;               // 0..11, 192 K each
    int tid = threadIdx.x;
    int tx = tid & 15;                   // 4 cols
    int ty = tid >> 4;                   // 4 rows
    int row0 = mblk * 64;
    int k0 = spl * KSPL;

    __shared__ float As[32][64];         // [k][row]
    __shared__ float Bs[32][64];         // [k][col]

    float acc[4][4];
    #pragma unroll
    for (int i = 0; i < 4; i++)
        #pragma unroll
        for (int j = 0; j < 4; j++) acc[i][j] = 0.f;

    for (int kk = 0; kk < KSPL; kk += 32) {
        // A: 32 k-rows x 64 n = 512 float4, contiguous per k-row
        {
            int k = tid >> 4, q = tid & 15;           // 2 passes of 16 k
            const float* srcA = g_roiT + (size_t)(k0 + kk) * NROW + row0;
            *(float4*)&As[k][q * 4] =
                *(const float4*)(srcA + (size_t)k * NROW + q * 4);
            *(float4*)&As[k + 16][q * 4] =
                *(const float4*)(srcA + (size_t)(k + 16) * NROW + q * 4);
            const float* srcB = g_W2t + (size_t)(k0 + kk) * CC;
            *(float4*)&Bs[k][q * 4] =
                *(const float4*)(srcB + (size_t)k * CC + q * 4);
            *(float4*)&Bs[k + 16][q * 4] =
                *(const float4*)(srcB + (size_t)(k + 16) * CC + q * 4);
        }
        __syncthreads();
        #pragma unroll
        for (int k = 0; k < 32; k++) {
            float4 a = *(const float4*)&As[k][ty * 4];
            float4 bv = *(const float4*)&Bs[k][tx * 4];
            acc[0][0] += a.x * bv.x; acc[0][1] += a.x * bv.y;
            acc[0][2] += a.x * bv.z; acc[0][3] += a.x * bv.w;
            acc[1][0] += a.y * bv.x; acc[1][1] += a.y * bv.y;
            acc[1][2] += a.y * bv.z; acc[1][3] += a.y * bv.w;
            acc[2][0] += a.z * bv.x; acc[2][1] += a.z * bv.y;
            acc[2][2] += a.z * bv.z; acc[2][3] += a.z * bv.w;
            acc[3][0] += a.w * bv.x; acc[3][1] += a.w * bv.y;
            acc[3][2] += a.w * bv.z; acc[3][3] += a.w * bv.w;
        }
        __syncthreads();
    }
    #pragma unroll
    for (int i = 0; i < 4; i++) {
        float4 v = make_float4(acc[i][0], acc[i][1], acc[i][2], acc[i][3]);
        *(float4*)&g_xp_part[spl][(row0 + ty * 4 + i) * CC + tx * 4] = v;
    }
}

// ---------------- K4b: reduce split partials + bias ----------------
__global__ void reduce_xp_kernel() {
    int idx = blockIdx.x * 256 + threadIdx.x;
    if (idx >= NROW * CC) return;
    int o = idx & 63;
    float s = g_b2[o];
    #pragma unroll
    for (int sp_ = 0; sp_ < NSPLIT; sp_++) s += g_xp_part[sp_][idx];
    g_xp[idx] = s;
}

// ---------------- K5: attention ----------------
__global__ void attn_kernel() {
    extern __shared__ float sm[];
    float* xfs = sm;                      // [64][251]
    float* xps = sm + 64 * 251;           // [16][64]
    float* wbf = xps + 16 * 64;           // [16][250]

    int lq = blockIdx.x;
    int b = blockIdx.y;
    int tid = threadIdx.x;
    int w = tid >> 5, t = tid & 31;
    int lane = lq * 16 + w;
    int n = b * LANES_ + lane;

    for (int i = tid; i < CC * NPOOL; i += 512) {
        int c = i / NPOOL, r = i % NPOOL;
        xfs[c * 251 + r] = g_xf[(b * CC + c) * NPOOL + r];
    }
    for (int o = t; o < CC; o += 32)
        xps[w * CC + o] = g_xp[n * CC + o];
    __syncthreads();

    float sc[8];
    float mx = -1e30f;
    #pragma unroll
    for (int j = 0; j < 8; j++) {
        int r = t + 32 * j;
        if (r < NPOOL) {
            float s = 0.f;
            #pragma unroll 8
            for (int c = 0; c < CC; c++) s += xps[w * CC + c] * xfs[c * 251 + r];
            s *= 0.125f;
            sc[j] = s;
            mx = fmaxf(mx, s);
        } else sc[j] = -1e30f;
    }
    #pragma unroll
    for (int off = 16; off > 0; off >>= 1)
        mx = fmaxf(mx, __shfl_xor_sync(0xffffffffu, mx, off));
    float sum = 0.f;
    #pragma unroll
    for (int j = 0; j < 8; j++) { sc[j] = __expf(sc[j] - mx); sum += sc[j]; }
    #pragma unroll
    for (int off = 16; off > 0; off >>= 1)
        sum += __shfl_xor_sync(0xffffffffu, sum, off);
    float inv = 1.0f / sum;
    #pragma unroll
    for (int j = 0; j < 8; j++) {
        int r = t + 32 * j;
        if (r < NPOOL) wbf[w * NPOOL + r] = sc[j] * inv;
    }
    __syncwarp();

    for (int c = t; c < CC; c += 32) {
        float s = 0.f;
        #pragma unroll 10
        for (int r = 0; r < NPOOL; r++) s += wbf[w * NPOOL + r] * xfs[c * 251 + r];
        g_gv[b * (LANES_ * CC) + lane * CC + c] = s;
    }
}

// ---------------- K6: conv1x1 + relu + broadcast-add prior ----------------
__global__ void final_kernel(const float* __restrict__ w1x1,
                             const float* __restrict__ b1x1,
                             const float* __restrict__ prior,
                             float* __restrict__ out) {
    int og = blockIdx.x;
    int b = blockIdx.y;
    int tid = threadIdx.x;
    int w = tid >> 5, t = tid & 31;

    __shared__ float gvs[4096];
    __shared__ float vals[8];
    for (int i = tid; i < 4096; i += 256) gvs[i] = g_gv[b * 4096 + i];
    __syncthreads();

    int o = og * 8 + w;
    const float* wrow = w1x1 + (size_t)o * 4096;
    float s = 0.f;
    for (int j = t * 4; j < 4096; j += 128) {
        float4 wv = *(const float4*)&wrow[j];
        float4 gv = *(const float4*)&gvs[j];
        s += wv.x * gv.x + wv.y * gv.y + wv.z * gv.z + wv.w * gv.w;
    }
    #pragma unroll
    for (int off = 16; off > 0; off >>= 1)
        s += __shfl_xor_sync(0xffffffffu, s, off);
    if (t == 0) vals[w] = fmaxf(s + b1x1[o], 0.f);
    __syncthreads();

    for (int i = tid; i < 8 * PE_; i += 256) {
        int oo = i / PE_, e = i % PE_;
        int oabs = og * 8 + oo;
        int idx = b * (CC * PE_) + oabs * PE_ + e;
        out[idx] = vals[oo] + prior[idx];
    }
}

// ---------------- launch ----------------
extern "C" void kernel_launch(void* const* d_in, const int* in_sizes, int n_in,
                              void* d_out, int out_size) {
    const float* feat    = (const float*)d_in[0];
    const float* prior   = (const float*)d_in[1];
    const float* conv_w  = (const float*)d_in[2];
    const float* conv_b  = (const float*)d_in[3];
    const float* fc_w    = (const float*)d_in[4];
    const float* fc_b    = (const float*)d_in[5];
    const float* w1x1    = (const float*)d_in[6];
    const float* b1x1    = (const float*)d_in[7];
    float* out = (float*)d_out;

    const int attn_smem = (64 * 251 + 16 * 64 + 16 * 250) * (int)sizeof(float);
    cudaFuncSetAttribute(attn_kernel, cudaFuncAttributeMaxDynamicSharedMemorySize,
                         attn_smem);

    xprep_kernel<<<(BB * SPP * LANES_ + 255) / 256, 256>>>(prior);
    w2_kernel<<<dim3(CC, 4), 256>>>(conv_w, conv_b, fc_w, fc_b);
    pool_kernel<<<(BB * CC * NPOOL + 255) / 256, 256>>>(feat);
    gather_kernel<<<dim3(SPP, 4, BB), 256>>>(feat);
    gemm_kernel<<<dim3(32, NSPLIT), 256>>>();
    reduce_xp_kernel<<<(NROW * CC + 255) / 256, 256>>>();
    attn_kernel<<<dim3(4, BB), 512, attn_smem>>>();
    final_kernel<<<dim3(8, BB), 256>>>(w1x1, b1x1, prior, out);
}

// round 5
// speedup vs baseline: 1.7497x; 1.0594x over previous
#include <cuda_runtime.h>
#include <math.h>

// ---------------- problem constants ----------------
#define BB     32
#define CC     64
#define FHH    80
#define FWW    200
#define SPP    36
#define LANES_ 64
#define PE_    78
#define RH_    10
#define RW_    25
#define NPOOL  250
#define KDIM   2304          // SPP * CC   (k = s*64 + c)
#define NROW   2048          // B * LANES
#define NSPLIT 12
#define KSPL   192           // KDIM / NSPLIT

// ---------------- device scratch ----------------
__device__ float g_xf[BB * CC * NPOOL];             // pooled features [b][c][r]
__device__ float g_W2t[KDIM * CC];                  // fused weight, k-major [k][o]
__device__ float g_b2[CC];
__device__ float g_roiT[(size_t)KDIM * NROW];       // roi, k-major [k][n]
__device__ float g_xp_part[NSPLIT][NROW * CC];
__device__ float g_gv[BB * LANES_ * CC];
__device__ unsigned int g_xidx[BB * SPP * LANES_];  // packed xf | xc<<16

// ---------------- K0: precompute per-(b,sp,lane) x indices ----------------
__global__ void xprep_kernel(const float* __restrict__ prior) {
    int idx = blockIdx.x * 256 + threadIdx.x;
    if (idx >= BB * SPP * LANES_) return;
    int b = idx / (SPP * LANES_);
    int rem = idx % (SPP * LANES_);
    int sp = rem / LANES_;
    int lane = rem % LANES_;
    float xv = prior[(b * LANES_ + lane) * PE_ + 6 + 2 * sp] * 0.25f;
    xv = fminf(xv, 199.0f);
    unsigned int xf = (unsigned int)(int)floorf(xv);
    unsigned int xc = (unsigned int)(int)ceilf(xv);
    g_xidx[idx] = xf | (xc << 16);
}

// ---------------- K1: fused pool + gather, one pass over feature map -------
// block = (c, b): load the whole 80x200 channel image into smem (one
// contiguous 64KB copy), then pool (250 outputs) and gather (36x64 outputs)
// entirely from smem. 2048 blocks -> bandwidth-bound streaming.
__global__ void __launch_bounds__(256) pool_gather_kernel(const float* __restrict__ f) {
    extern __shared__ float sm[];
    float* img = sm;                             // [80*200]
    unsigned int* xid = (unsigned int*)(sm + FHH * FWW);  // [36*64]

    int c = blockIdx.x;
    int b = blockIdx.y;
    int tid = threadIdx.x;

    // contiguous copy: 16000 floats = 4000 float4
    {
        const float4* src = (const float4*)(f + (size_t)(b * CC + c) * (FHH * FWW));
        float4* dst = (float4*)img;
        #pragma unroll 4
        for (int i = tid; i < 4000; i += 256) dst[i] = src[i];
    }
    for (int i = tid; i < SPP * LANES_; i += 256)
        xid[i] = g_xidx[b * (SPP * LANES_) + i];
    __syncthreads();

    // pool: 250 outputs
    if (tid < NPOOL) {
        int rh = tid / RW_, rw = tid % RW_;
        const float* base = img + rh * 8 * FWW + rw * 8;
        float s = 0.f;
        #pragma unroll
        for (int rr = 0; rr < 8; rr++) {
            float4 a = *(const float4*)(base + rr * FWW);
            float4 bq = *(const float4*)(base + rr * FWW + 4);
            s += a.x + a.y + a.z + a.w + bq.x + bq.y + bq.z + bq.w;
        }
        g_xf[(size_t)(b * CC + c) * NPOOL + tid] = s * (1.0f / 64.0f);
    }

    // gather: 36*64 = 2304 outputs, 9 iterations
    #pragma unroll
    for (int it = 0; it < 9; it++) {
        int i = tid + it * 256;
        int sp = i >> 6, lane = i & 63;
        float yv = 0.25f * (319.0f - (320.0f / 71.0f) * (float)(2 * sp));
        yv = fminf(yv, 79.0f);
        int yf = (int)floorf(yv);
        int yc = (int)ceilf(yv);
        unsigned int p = xid[i];
        int xf = (int)(p & 0xffffu), xc = (int)(p >> 16);
        const float* rA = img + yf * FWW;
        const float* rB = img + yc * FWW;
        float v = rA[xf] + rA[xc] + rB[xf] + rB[xc];
        g_roiT[(size_t)(sp * CC + c) * NROW + b * LANES_ + lane] = 0.25f * v;
    }
}

// ---------------- K2: fuse conv1d + fc into W2t / b2 ----------------
__global__ void w2_kernel(const float* __restrict__ conv_w,
                          const float* __restrict__ conv_b,
                          const float* __restrict__ fc_w,
                          const float* __restrict__ fc_b) {
    int o = blockIdx.x;      // 0..63
    int q = blockIdx.y;      // 0..3 (c1 group of 16)
    int tid = threadIdx.x;
    __shared__ float fcrow[2048];
    __shared__ float convs[64 * 16 * 5];     // [c2][c1l][k]
    __shared__ float bpart[64];

    for (int i = tid; i < 2048; i += 256) fcrow[i] = fc_w[o * 2048 + i];
    for (int i = tid; i < 5120; i += 256) {
        int c2 = i / 80, rem = i % 80;
        int c1l = rem / 5, k = rem % 5;
        convs[i] = conv_w[(c2 * CC + q * 16 + c1l) * 5 + k];
    }
    __syncthreads();

    for (int i = tid; i < 16 * SPP; i += 256) {
        int c1l = i / SPP, s = i % SPP;
        float acc = 0.f;
        for (int c2 = 0; c2 < CC; c2++) {
            const float* w5 = &convs[c2 * 80 + c1l * 5];
            const float* fr = &fcrow[c2 * 32];
            #pragma unroll
            for (int k = 0; k < 5; k++) {
                int p = s - k;
                if (p >= 0 && p < 32) acc += w5[k] * fr[p];
            }
        }
        g_W2t[(size_t)(s * CC + q * 16 + c1l) * CC + o] = acc;
    }

    if (q == 0) {
        if (tid < CC) {
            float s = 0.f;
            #pragma unroll
            for (int p = 0; p < 32; p++) s += fcrow[tid * 32 + p];
            bpart[tid] = s * conv_b[tid];
        }
        __syncthreads();
        if (tid == 0) {
            float s = fc_b[o];
            for (int j = 0; j < CC; j++) s += bpart[j];
            g_b2[o] = s;
        }
    }
}

// ---------------- K4: Xp_part = ROI^T(k-major) x W2t, K-split --------------
__global__ void __launch_bounds__(256) gemm_kernel() {
    int mblk = blockIdx.x;               // 0..31, 64 rows each
    int spl  = blockIdx.y;               // 0..11, 192 K each
    int tid = threadIdx.x;
    int tx = tid & 15;                   // 4 cols
    int ty = tid >> 4;                   // 4 rows
    int row0 = mblk * 64;
    int k0 = spl * KSPL;

    __shared__ float As[32][64];         // [k][row]
    __shared__ float Bs[32][64];         // [k][col]

    float acc[4][4];
    #pragma unroll
    for (int i = 0; i < 4; i++)
        #pragma unroll
        for (int j = 0; j < 4; j++) acc[i][j] = 0.f;

    for (int kk = 0; kk < KSPL; kk += 32) {
        {
            int k = tid >> 4, q = tid & 15;
            const float* srcA = g_roiT + (size_t)(k0 + kk) * NROW + row0;
            *(float4*)&As[k][q * 4] =
                *(const float4*)(srcA + (size_t)k * NROW + q * 4);
            *(float4*)&As[k + 16][q * 4] =
                *(const float4*)(srcA + (size_t)(k + 16) * NROW + q * 4);
            const float* srcB = g_W2t + (size_t)(k0 + kk) * CC;
            *(float4*)&Bs[k][q * 4] =
                *(const float4*)(srcB + (size_t)k * CC + q * 4);
            *(float4*)&Bs[k + 16][q * 4] =
                *(const float4*)(srcB + (size_t)(k + 16) * CC + q * 4);
        }
        __syncthreads();
        #pragma unroll
        for (int k = 0; k < 32; k++) {
            float4 a = *(const float4*)&As[k][ty * 4];
            float4 bv = *(const float4*)&Bs[k][tx * 4];
            acc[0][0] += a.x * bv.x; acc[0][1] += a.x * bv.y;
            acc[0][2] += a.x * bv.z; acc[0][3] += a.x * bv.w;
            acc[1][0] += a.y * bv.x; acc[1][1] += a.y * bv.y;
            acc[1][2] += a.y * bv.z; acc[1][3] += a.y * bv.w;
            acc[2][0] += a.z * bv.x; acc[2][1] += a.z * bv.y;
            acc[2][2] += a.z * bv.z; acc[2][3] += a.z * bv.w;
            acc[3][0] += a.w * bv.x; acc[3][1] += a.w * bv.y;
            acc[3][2] += a.w * bv.z; acc[3][3] += a.w * bv.w;
        }
        __syncthreads();
    }
    #pragma unroll
    for (int i = 0; i < 4; i++) {
        float4 v = make_float4(acc[i][0], acc[i][1], acc[i][2], acc[i][3]);
        *(float4*)&g_xp_part[spl][(row0 + ty * 4 + i) * CC + tx * 4] = v;
    }
}

// ---------------- K5: attention (folds split-K reduction) ----------------
__global__ void attn_kernel() {
    extern __shared__ float sm[];
    float* xfs = sm;                      // [64][251]
    float* xps = sm + 64 * 251;           // [16][64]
    float* wbf = xps + 16 * 64;           // [16][250]

    int lq = blockIdx.x;
    int b = blockIdx.y;
    int tid = threadIdx.x;
    int w = tid >> 5, t = tid & 31;
    int lane = lq * 16 + w;
    int n = b * LANES_ + lane;

    for (int i = tid; i < CC * NPOOL; i += 512) {
        int c = i / NPOOL, r = i % NPOOL;
        xfs[c * 251 + r] = g_xf[(b * CC + c) * NPOOL + r];
    }
    for (int o = t; o < CC; o += 32) {
        float s = g_b2[o];
        #pragma unroll
        for (int sp_ = 0; sp_ < NSPLIT; sp_++) s += g_xp_part[sp_][n * CC + o];
        xps[w * CC + o] = s;
    }
    __syncthreads();

    float sc[8];
    float mx = -1e30f;
    #pragma unroll
    for (int j = 0; j < 8; j++) {
        int r = t + 32 * j;
        if (r < NPOOL) {
            float s = 0.f;
            #pragma unroll 8
            for (int c = 0; c < CC; c++) s += xps[w * CC + c] * xfs[c * 251 + r];
            s *= 0.125f;
            sc[j] = s;
            mx = fmaxf(mx, s);
        } else sc[j] = -1e30f;
    }
    #pragma unroll
    for (int off = 16; off > 0; off >>= 1)
        mx = fmaxf(mx, __shfl_xor_sync(0xffffffffu, mx, off));
    float sum = 0.f;
    #pragma unroll
    for (int j = 0; j < 8; j++) { sc[j] = __expf(sc[j] - mx); sum += sc[j]; }
    #pragma unroll
    for (int off = 16; off > 0; off >>= 1)
        sum += __shfl_xor_sync(0xffffffffu, sum, off);
    float inv = 1.0f / sum;
    #pragma unroll
    for (int j = 0; j < 8; j++) {
        int r = t + 32 * j;
        if (r < NPOOL) wbf[w * NPOOL + r] = sc[j] * inv;
    }
    __syncwarp();

    for (int c = t; c < CC; c += 32) {
        float s = 0.f;
        #pragma unroll 10
        for (int r = 0; r < NPOOL; r++) s += wbf[w * NPOOL + r] * xfs[c * 251 + r];
        g_gv[b * (LANES_ * CC) + lane * CC + c] = s;
    }
}

// ---------------- K6: conv1x1 + relu + broadcast-add prior ----------------
__global__ void final_kernel(const float* __restrict__ w1x1,
                             const float* __restrict__ b1x1,
                             const float* __restrict__ prior,
                             float* __restrict__ out) {
    int og = blockIdx.x;
    int b = blockIdx.y;
    int tid = threadIdx.x;
    int w = tid >> 5, t = tid & 31;

    __shared__ float gvs[4096];
    __shared__ float vals[8];
    for (int i = tid; i < 4096; i += 256) gvs[i] = g_gv[b * 4096 + i];
    __syncthreads();

    int o = og * 8 + w;
    const float* wrow = w1x1 + (size_t)o * 4096;
    float s = 0.f;
    for (int j = t * 4; j < 4096; j += 128) {
        float4 wv = *(const float4*)&wrow[j];
        float4 gv = *(const float4*)&gvs[j];
        s += wv.x * gv.x + wv.y * gv.y + wv.z * gv.z + wv.w * gv.w;
    }
    #pragma unroll
    for (int off = 16; off > 0; off >>= 1)
        s += __shfl_xor_sync(0xffffffffu, s, off);
    if (t == 0) vals[w] = fmaxf(s + b1x1[o], 0.f);
    __syncthreads();

    for (int i = tid; i < 8 * PE_; i += 256) {
        int oo = i / PE_, e = i % PE_;
        int oabs = og * 8 + oo;
        int idx = b * (CC * PE_) + oabs * PE_ + e;
        out[idx] = vals[oo] + prior[idx];
    }
}

// ---------------- launch ----------------
extern "C" void kernel_launch(void* const* d_in, const int* in_sizes, int n_in,
                              void* d_out, int out_size) {
    const float* feat    = (const float*)d_in[0];
    const float* prior   = (const float*)d_in[1];
    const float* conv_w  = (const float*)d_in[2];
    const float* conv_b  = (const float*)d_in[3];
    const float* fc_w    = (const float*)d_in[4];
    const float* fc_b    = (const float*)d_in[5];
    const float* w1x1    = (const float*)d_in[6];
    const float* b1x1    = (const float*)d_in[7];
    float* out = (float*)d_out;

    const int pg_smem = (FHH * FWW) * (int)sizeof(float)
                      + (SPP * LANES_) * (int)sizeof(unsigned int);
    const int attn_smem = (64 * 251 + 16 * 64 + 16 * 250) * (int)sizeof(float);
    cudaFuncSetAttribute(pool_gather_kernel,
                         cudaFuncAttributeMaxDynamicSharedMemorySize, pg_smem);
    cudaFuncSetAttribute(attn_kernel,
                         cudaFuncAttributeMaxDynamicSharedMemorySize, attn_smem);

    xprep_kernel<<<(BB * SPP * LANES_ + 255) / 256, 256>>>(prior);
    w2_kernel<<<dim3(CC, 4), 256>>>(conv_w, conv_b, fc_w, fc_b);
    pool_gather_kernel<<<dim3(CC, BB), 256, pg_smem>>>(feat);
    gemm_kernel<<<dim3(32, NSPLIT), 256>>>();
    attn_kernel<<<dim3(4, BB), 512, attn_smem>>>();
    final_kernel<<<dim3(8, BB), 256>>>(w1x1, b1x1, prior, out);
}

// round 8
// speedup vs baseline: 1.8838x; 1.0767x over previous
#include <cuda_runtime.h>
#include <math.h>
#include <stdint.h>

// ---------------- problem constants ----------------
#define BB     32
#define CC     64
#define FHH    80
#define FWW    200
#define SPP    36
#define LANES_ 64
#define PE_    78
#define RH_    10
#define RW_    25
#define NPOOL  250
#define KDIM   2304          // SPP * CC   (k = s*64 + c)
#define NROW   2048          // B * LANES
#define NSPLIT 12
#define KSPL   192           // KDIM / NSPLIT

// ---------------- device scratch ----------------
__device__ float g_xf[BB * CC * NPOOL];             // pooled features [b][c][r]
__device__ float g_W2t[KDIM * CC];                  // fused weight, k-major [k][o]
__device__ float g_b2[CC];
__device__ float g_roiT[(size_t)KDIM * NROW];       // roi, k-major [k][n]
__device__ float g_xp_part[NSPLIT][NROW * CC];
__device__ float g_gv[BB * LANES_ * CC];
__device__ unsigned int g_xidx[BB * SPP * LANES_];  // packed xf | xc<<16

// ---------------- K0: precompute per-(b,sp,lane) x indices ----------------
__global__ void xprep_kernel(const float* __restrict__ prior) {
    int idx = blockIdx.x * 256 + threadIdx.x;
    if (idx >= BB * SPP * LANES_) return;
    int b = idx / (SPP * LANES_);
    int rem = idx % (SPP * LANES_);
    int sp = rem / LANES_;
    int lane = rem % LANES_;
    float xv = prior[(b * LANES_ + lane) * PE_ + 6 + 2 * sp] * 0.25f;
    xv = fminf(xv, 199.0f);
    unsigned int xf = (unsigned int)(int)floorf(xv);
    unsigned int xc = (unsigned int)(int)ceilf(xv);
    g_xidx[idx] = xf | (xc << 16);
}

// ---------------- K1: fused pool + gather, one pass over feature map -------
__global__ void __launch_bounds__(256) pool_gather_kernel(const float* __restrict__ f) {
    extern __shared__ float sm[];
    float* img = sm;                             // [80*200]
    unsigned int* xid = (unsigned int*)(sm + FHH * FWW);  // [36*64]

    int c = blockIdx.x;
    int b = blockIdx.y;
    int tid = threadIdx.x;

    {
        const float4* src = (const float4*)(f + (size_t)(b * CC + c) * (FHH * FWW));
        float4* dst = (float4*)img;
        #pragma unroll 4
        for (int i = tid; i < 4000; i += 256) dst[i] = src[i];
    }
    for (int i = tid; i < SPP * LANES_; i += 256)
        xid[i] = g_xidx[b * (SPP * LANES_) + i];
    __syncthreads();

    if (tid < NPOOL) {
        int rh = tid / RW_, rw = tid % RW_;
        const float* base = img + rh * 8 * FWW + rw * 8;
        float s = 0.f;
        #pragma unroll
        for (int rr = 0; rr < 8; rr++) {
            float4 a = *(const float4*)(base + rr * FWW);
            float4 bq = *(const float4*)(base + rr * FWW + 4);
            s += a.x + a.y + a.z + a.w + bq.x + bq.y + bq.z + bq.w;
        }
        g_xf[(size_t)(b * CC + c) * NPOOL + tid] = s * (1.0f / 64.0f);
    }

    #pragma unroll
    for (int it = 0; it < 9; it++) {
        int i = tid + it * 256;
        int sp = i >> 6, lane = i & 63;
        float yv = 0.25f * (319.0f - (320.0f / 71.0f) * (float)(2 * sp));
        yv = fminf(yv, 79.0f);
        int yf = (int)floorf(yv);
        int yc = (int)ceilf(yv);
        unsigned int p = xid[i];
        int xf = (int)(p & 0xffffu), xc = (int)(p >> 16);
        const float* rA = img + yf * FWW;
        const float* rB = img + yc * FWW;
        float v = rA[xf] + rA[xc] + rB[xf] + rB[xc];
        g_roiT[(size_t)(sp * CC + c) * NROW + b * LANES_ + lane] = 0.25f * v;
    }
}

// ---------------- K2: fuse conv1d + fc into W2t / b2 ----------------
__global__ void w2_kernel(const float* __restrict__ conv_w,
                          const float* __restrict__ conv_b,
                          const float* __restrict__ fc_w,
                          const float* __restrict__ fc_b) {
    int o = blockIdx.x;      // 0..63
    int q = blockIdx.y;      // 0..3 (c1 group of 16)
    int tid = threadIdx.x;
    __shared__ float fcrow[2048];
    __shared__ float convs[64 * 16 * 5];     // [c2][c1l][k]
    __shared__ float bpart[64];

    for (int i = tid; i < 2048; i += 256) fcrow[i] = fc_w[o * 2048 + i];
    for (int i = tid; i < 5120; i += 256) {
        int c2 = i / 80, rem = i % 80;
        int c1l = rem / 5, k = rem % 5;
        convs[i] = conv_w[(c2 * CC + q * 16 + c1l) * 5 + k];
    }
    __syncthreads();

    for (int i = tid; i < 16 * SPP; i += 256) {
        int c1l = i / SPP, s = i % SPP;
        float acc = 0.f;
        for (int c2 = 0; c2 < CC; c2++) {
            const float* w5 = &convs[c2 * 80 + c1l * 5];
            const float* fr = &fcrow[c2 * 32];
            #pragma unroll
            for (int k = 0; k < 5; k++) {
                int p = s - k;
                if (p >= 0 && p < 32) acc += w5[k] * fr[p];
            }
        }
        g_W2t[(size_t)(s * CC + q * 16 + c1l) * CC + o] = acc;
    }

    if (q == 0) {
        if (tid < CC) {
            float s = 0.f;
            #pragma unroll
            for (int p = 0; p < 32; p++) s += fcrow[tid * 32 + p];
            bpart[tid] = s * conv_b[tid];
        }
        __syncthreads();
        if (tid == 0) {
            float s = fc_b[o];
            for (int j = 0; j < CC; j++) s += bpart[j];
            g_b2[o] = s;
        }
    }
}

// ---------------- K4: tf32 tensor-core GEMM, K-split ----------------
// Xp_part = ROI^T(k-major) x W2t.  Block tile 64x64, 8 warps (16x32 each),
// mma.sync.m16n8k8 tf32. Operands converted to tf32 bits AT SMEM-LOAD TIME;
// smem holds tf32 bit patterns (stride 72 -> conflict-free LDS.32).
__device__ __forceinline__ uint32_t f2tf32(float x) {
    uint32_t u;
    asm("cvt.rna.tf32.f32 %0, %1;" : "=r"(u) : "f"(x));
    return u;
}

__device__ __forceinline__ uint4 cvt4(float4 v) {
    uint4 o;
    o.x = f2tf32(v.x); o.y = f2tf32(v.y);
    o.z = f2tf32(v.z); o.w = f2tf32(v.w);
    return o;
}

__global__ void __launch_bounds__(256) gemm_kernel() {
    int mblk = blockIdx.x;               // 0..31, 64 rows each
    int spl  = blockIdx.y;               // 0..11, 192 K each
    int tid = threadIdx.x;
    int wid = tid >> 5;
    int t = tid & 31;
    int row0 = mblk * 64;
    int k0 = spl * KSPL;

    int warp_m = (wid & 3) * 16;         // 0,16,32,48
    int warp_n = (wid >> 2) * 32;        // 0,32
    int g = t >> 2;                      // 0..7
    int r = t & 3;                       // 0..3

    __shared__ uint32_t As[32][72];      // [k][m], tf32 bits
    __shared__ uint32_t Bs[32][72];      // [k][n], tf32 bits

    float acc[4][4];                     // [n-tile j][c0..c3]
    #pragma unroll
    for (int j = 0; j < 4; j++)
        #pragma unroll
        for (int i = 0; i < 4; i++) acc[j][i] = 0.f;

    for (int kk = 0; kk < KSPL; kk += 32) {
        {
            int k = tid >> 4, q = tid & 15;
            const float* srcA = g_roiT + (size_t)(k0 + kk) * NROW + row0;
            *(uint4*)&As[k][q * 4] =
                cvt4(*(const float4*)(srcA + (size_t)k * NROW + q * 4));
            *(uint4*)&As[k + 16][q * 4] =
                cvt4(*(const float4*)(srcA + (size_t)(k + 16) * NROW + q * 4));
            const float* srcB = g_W2t + (size_t)(k0 + kk) * CC;
            *(uint4*)&Bs[k][q * 4] =
                cvt4(*(const float4*)(srcB + (size_t)k * CC + q * 4));
            *(uint4*)&Bs[k + 16][q * 4] =
                cvt4(*(const float4*)(srcB + (size_t)(k + 16) * CC + q * 4));
        }
        __syncthreads();
        #pragma unroll
        for (int ks = 0; ks < 32; ks += 8) {
            // A fragment (m16 k8): rows g,g+8 / k-cols r,r+4
            uint32_t a0 = As[ks + r][warp_m + g];
            uint32_t a1 = As[ks + r][warp_m + g + 8];
            uint32_t a2 = As[ks + 4 + r][warp_m + g];
            uint32_t a3 = As[ks + 4 + r][warp_m + g + 8];
            #pragma unroll
            for (int j = 0; j < 4; j++) {
                uint32_t b0 = Bs[ks + r][warp_n + j * 8 + g];
                uint32_t b1 = Bs[ks + 4 + r][warp_n + j * 8 + g];
                asm volatile(
                    "mma.sync.aligned.m16n8k8.row.col.f32.tf32.tf32.f32 "
                    "{%0,%1,%2,%3}, {%4,%5,%6,%7}, {%8,%9}, {%0,%1,%2,%3};"
                    : "+f"(acc[j][0]), "+f"(acc[j][1]),
                      "+f"(acc[j][2]), "+f"(acc[j][3])
                    : "r"(a0), "r"(a1), "r"(a2), "r"(a3),
                      "r"(b0), "r"(b1));
            }
        }
        __syncthreads();
    }

    // store: c0,c1 -> (row g, cols 2r,2r+1); c2,c3 -> (row g+8)
    float* outp = &g_xp_part[spl][0];
    #pragma unroll
    for (int j = 0; j < 4; j++) {
        int colb = warp_n + j * 8 + 2 * r;
        int rowa = row0 + warp_m + g;
        *(float2*)&outp[(size_t)rowa * CC + colb] =
            make_float2(acc[j][0], acc[j][1]);
        *(float2*)&outp[(size_t)(rowa + 8) * CC + colb] =
            make_float2(acc[j][2], acc[j][3]);
    }
}

// ---------------- K5: attention (folds split-K reduction) ----------------
__global__ void attn_kernel() {
    extern __shared__ float sm[];
    float* xfs = sm;                      // [64][251]
    float* xps = sm + 64 * 251;           // [16][64]
    float* wbf = xps + 16 * 64;           // [16][250]

    int lq = blockIdx.x;
    int b = blockIdx.y;
    int tid = threadIdx.x;
    int w = tid >> 5, t = tid & 31;
    int lane = lq * 16 + w;
    int n = b * LANES_ + lane;

    for (int i = tid; i < CC * NPOOL; i += 512) {
        int c = i / NPOOL, r = i % NPOOL;
        xfs[c * 251 + r] = g_xf[(b * CC + c) * NPOOL + r];
    }
    for (int o = t; o < CC; o += 32) {
        float s = g_b2[o];
        #pragma unroll
        for (int sp_ = 0; sp_ < NSPLIT; sp_++) s += g_xp_part[sp_][n * CC + o];
        xps[w * CC + o] = s;
    }
    __syncthreads();

    float sc[8];
    float mx = -1e30f;
    #pragma unroll
    for (int j = 0; j < 8; j++) {
        int r = t + 32 * j;
        if (r < NPOOL) {
            float s = 0.f;
            #pragma unroll 8
            for (int c = 0; c < CC; c++) s += xps[w * CC + c] * xfs[c * 251 + r];
            s *= 0.125f;
            sc[j] = s;
            mx = fmaxf(mx, s);
        } else sc[j] = -1e30f;
    }
    #pragma unroll
    for (int off = 16; off > 0; off >>= 1)
        mx = fmaxf(mx, __shfl_xor_sync(0xffffffffu, mx, off));
    float sum = 0.f;
    #pragma unroll
    for (int j = 0; j < 8; j++) { sc[j] = __expf(sc[j] - mx); sum += sc[j]; }
    #pragma unroll
    for (int off = 16; off > 0; off >>= 1)
        sum += __shfl_xor_sync(0xffffffffu, sum, off);
    float inv = 1.0f / sum;
    #pragma unroll
    for (int j = 0; j < 8; j++) {
        int r = t + 32 * j;
        if (r < NPOOL) wbf[w * NPOOL + r] = sc[j] * inv;
    }
    __syncwarp();

    for (int c = t; c < CC; c += 32) {
        float s = 0.f;
        #pragma unroll 10
        for (int r = 0; r < NPOOL; r++) s += wbf[w * NPOOL + r] * xfs[c * 251 + r];
        g_gv[b * (LANES_ * CC) + lane * CC + c] = s;
    }
}

// ---------------- K6: conv1x1 + relu + broadcast-add prior ----------------
__global__ void final_kernel(const float* __restrict__ w1x1,
                             const float* __restrict__ b1x1,
                             const float* __restrict__ prior,
                             float* __restrict__ out) {
    int og = blockIdx.x;
    int b = blockIdx.y;
    int tid = threadIdx.x;
    int w = tid >> 5, t = tid & 31;

    __shared__ float gvs[4096];
    __shared__ float vals[8];
    for (int i = tid; i < 4096; i += 256) gvs[i] = g_gv[b * 4096 + i];
    __syncthreads();

    int o = og * 8 + w;
    const float* wrow = w1x1 + (size_t)o * 4096;
    float s = 0.f;
    for (int j = t * 4; j < 4096; j += 128) {
        float4 wv = *(const float4*)&wrow[j];
        float4 gv = *(const float4*)&gvs[j];
        s += wv.x * gv.x + wv.y * gv.y + wv.z * gv.z + wv.w * gv.w;
    }
    #pragma unroll
    for (int off = 16; off > 0; off >>= 1)
        s += __shfl_xor_sync(0xffffffffu, s, off);
    if (t == 0) vals[w] = fmaxf(s + b1x1[o], 0.f);
    __syncthreads();

    for (int i = tid; i < 8 * PE_; i += 256) {
        int oo = i / PE_, e = i % PE_;
        int oabs = og * 8 + oo;
        int idx = b * (CC * PE_) + oabs * PE_ + e;
        out[idx] = vals[oo] + prior[idx];
    }
}

// ---------------- launch ----------------
extern "C" void kernel_launch(void* const* d_in, const int* in_sizes, int n_in,
                              void* d_out, int out_size) {
    const float* feat    = (const float*)d_in[0];
    const float* prior   = (const float*)d_in[1];
    const float* conv_w  = (const float*)d_in[2];
    const float* conv_b  = (const float*)d_in[3];
    const float* fc_w    = (const float*)d_in[4];
    const float* fc_b    = (const float*)d_in[5];
    const float* w1x1    = (const float*)d_in[6];
    const float* b1x1    = (const float*)d_in[7];
    float* out = (float*)d_out;

    const int pg_smem = (FHH * FWW) * (int)sizeof(float)
                      + (SPP * LANES_) * (int)sizeof(unsigned int);
    const int attn_smem = (64 * 251 + 16 * 64 + 16 * 250) * (int)sizeof(float);
    cudaFuncSetAttribute(pool_gather_kernel,
                         cudaFuncAttributeMaxDynamicSharedMemorySize, pg_smem);
    cudaFuncSetAttribute(attn_kernel,
                         cudaFuncAttributeMaxDynamicSharedMemorySize, attn_smem);

    xprep_kernel<<<(BB * SPP * LANES_ + 255) / 256, 256>>>(prior);
    w2_kernel<<<dim3(CC, 4), 256>>>(conv_w, conv_b, fc_w, fc_b);
    pool_gather_kernel<<<dim3(CC, BB), 256, pg_smem>>>(feat);
    gemm_kernel<<<dim3(32, NSPLIT), 256>>>();
    attn_kernel<<<dim3(4, BB), 512, attn_smem>>>();
    final_kernel<<<dim3(8, BB), 256>>>(w1x1, b1x1, prior, out);
}

// round 9
// speedup vs baseline: 1.9795x; 1.0508x over previous
#include <cuda_runtime.h>
#include <math.h>
#include <stdint.h>

// ---------------- problem constants ----------------
#define BB     32
#define CC     64
#define FHH    80
#define FWW    200
#define SPP    36
#define LANES_ 64
#define PE_    78
#define RH_    10
#define RW_    25
#define NPOOL  250
#define KDIM   2304          // SPP * CC   (k = s*64 + c)
#define NROW   2048          // B * LANES
#define NSPLIT 12
#define KSPL   192           // KDIM / NSPLIT
#define NCHUNK 6             // KSPL / 32

// ---------------- device scratch ----------------
__device__ float g_xf[BB * CC * NPOOL];             // pooled features [b][c][r]
__device__ float g_W2t[KDIM * CC];                  // fused weight, k-major [k][o]
__device__ float g_b2[CC];
__device__ float g_roiT[(size_t)KDIM * NROW];       // roi, k-major [k][n]
__device__ float g_xp_part[NSPLIT][NROW * CC];
__device__ float g_gv[BB * LANES_ * CC];

__device__ __forceinline__ uint32_t smem_u32(const void* p) {
    uint32_t a;
    asm("{ .reg .u64 t; cvta.to.shared.u64 t, %1; cvt.u32.u64 %0, t; }"
        : "=r"(a) : "l"(p));
    return a;
}

// ---------------- K1: fused pool + gather (TMA bulk load + xprep inline) ---
// block = (c, b). One cp.async.bulk brings the 64KB channel image into smem;
// while it flies, threads compute the gather x-indices from prior.
__global__ void __launch_bounds__(256) pool_gather_kernel(
        const float* __restrict__ f, const float* __restrict__ prior) {
    extern __shared__ float sm[];
    float* img = sm;                                   // [16000]
    unsigned int* xid = (unsigned int*)(sm + FHH * FWW); // [2304]
    unsigned long long* mbar =
        (unsigned long long*)(sm + FHH * FWW + SPP * LANES_);

    int c = blockIdx.x;
    int b = blockIdx.y;
    int tid = threadIdx.x;

    uint32_t mbar_a = smem_u32(mbar);
    uint32_t img_a  = smem_u32(img);

    if (tid == 0) {
        asm volatile("mbarrier.init.shared.b64 [%0], %1;"
                     :: "r"(mbar_a), "r"(1) : "memory");
    }
    __syncthreads();

    if (tid == 0) {
        const float* src = f + (size_t)(b * CC + c) * (FHH * FWW);
        asm volatile("mbarrier.arrive.expect_tx.shared.b64 _, [%0], %1;"
                     :: "r"(mbar_a), "r"(FHH * FWW * 4) : "memory");
        asm volatile(
            "cp.async.bulk.shared::cluster.global.mbarrier::complete_tx::bytes "
            "[%0], [%1], %2, [%3];"
            :: "r"(img_a), "l"(src), "r"(FHH * FWW * 4), "r"(mbar_a)
            : "memory");
    }

    // overlap: compute gather x indices from prior (xprep folded in)
    for (int i = tid; i < SPP * LANES_; i += 256) {
        int sp = i >> 6, lane = i & 63;
        float xv = prior[(b * LANES_ + lane) * PE_ + 6 + 2 * sp] * 0.25f;
        xv = fminf(xv, 199.0f);
        unsigned int xf = (unsigned int)(int)floorf(xv);
        unsigned int xc = (unsigned int)(int)ceilf(xv);
        xid[i] = xf | (xc << 16);
    }

    // wait for TMA completion (phase 0)
    asm volatile(
        "{\n\t"
        ".reg .pred P;\n\t"
        "W%=:\n\t"
        "mbarrier.try_wait.parity.shared.b64 P, [%0], 0;\n\t"
        "@!P bra W%=;\n\t"
        "}"
        :: "r"(mbar_a) : "memory");
    __syncthreads();   // xid writes + barrier wait ordering for all threads

    // pool: 250 outputs
    if (tid < NPOOL) {
        int rh = tid / RW_, rw = tid % RW_;
        const float* base = img + rh * 8 * FWW + rw * 8;
        float s = 0.f;
        #pragma unroll
        for (int rr = 0; rr < 8; rr++) {
            float4 a = *(const float4*)(base + rr * FWW);
            float4 bq = *(const float4*)(base + rr * FWW + 4);
            s += a.x + a.y + a.z + a.w + bq.x + bq.y + bq.z + bq.w;
        }
        g_xf[(size_t)(b * CC + c) * NPOOL + tid] = s * (1.0f / 64.0f);
    }

    // gather: 36*64 = 2304 outputs
    #pragma unroll
    for (int it = 0; it < 9; it++) {
        int i = tid + it * 256;
        int sp = i >> 6, lane = i & 63;
        float yv = 0.25f * (319.0f - (320.0f / 71.0f) * (float)(2 * sp));
        yv = fminf(yv, 79.0f);
        int yf = (int)floorf(yv);
        int yc = (int)ceilf(yv);
        unsigned int p = xid[i];
        int xf = (int)(p & 0xffffu), xc = (int)(p >> 16);
        const float* rA = img + yf * FWW;
        const float* rB = img + yc * FWW;
        float v = rA[xf] + rA[xc] + rB[xf] + rB[xc];
        g_roiT[(size_t)(sp * CC + c) * NROW + b * LANES_ + lane] = 0.25f * v;
    }
}

// ---------------- K2: fuse conv1d + fc into W2t / b2 ----------------
__global__ void w2_kernel(const float* __restrict__ conv_w,
                          const float* __restrict__ conv_b,
                          const float* __restrict__ fc_w,
                          const float* __restrict__ fc_b) {
    int o = blockIdx.x;      // 0..63
    int q = blockIdx.y;      // 0..3 (c1 group of 16)
    int tid = threadIdx.x;
    __shared__ float fcrow[2048];
    __shared__ float convs[64 * 16 * 5];     // [c2][c1l][k]
    __shared__ float bpart[64];

    for (int i = tid; i < 2048; i += 256) fcrow[i] = fc_w[o * 2048 + i];
    for (int i = tid; i < 5120; i += 256) {
        int c2 = i / 80, rem = i % 80;
        int c1l = rem / 5, k = rem % 5;
        convs[i] = conv_w[(c2 * CC + q * 16 + c1l) * 5 + k];
    }
    __syncthreads();

    for (int i = tid; i < 16 * SPP; i += 256) {
        int c1l = i / SPP, s = i % SPP;
        float acc = 0.f;
        for (int c2 = 0; c2 < CC; c2++) {
            const float* w5 = &convs[c2 * 80 + c1l * 5];
            const float* fr = &fcrow[c2 * 32];
            #pragma unroll
            for (int k = 0; k < 5; k++) {
                int p = s - k;
                if (p >= 0 && p < 32) acc += w5[k] * fr[p];
            }
        }
        g_W2t[(size_t)(s * CC + q * 16 + c1l) * CC + o] = acc;
    }

    if (q == 0) {
        if (tid < CC) {
            float s = 0.f;
            #pragma unroll
            for (int p = 0; p < 32; p++) s += fcrow[tid * 32 + p];
            bpart[tid] = s * conv_b[tid];
        }
        __syncthreads();
        if (tid == 0) {
            float s = fc_b[o];
            for (int j = 0; j < CC; j++) s += bpart[j];
            g_b2[o] = s;
        }
    }
}

// ---------------- K4: tf32 tensor-core GEMM, K-split, double-buffered ------
__device__ __forceinline__ uint32_t f2tf32(float x) {
    uint32_t u;
    asm("cvt.rna.tf32.f32 %0, %1;" : "=r"(u) : "f"(x));
    return u;
}

__global__ void __launch_bounds__(256) gemm_kernel() {
    int mblk = blockIdx.x;               // 0..31, 64 rows each
    int spl  = blockIdx.y;               // 0..11, 192 K each
    int tid = threadIdx.x;
    int wid = tid >> 5;
    int t = tid & 31;
    int row0 = mblk * 64;
    int k0 = spl * KSPL;

    int warp_m = (wid & 3) * 16;         // 0,16,32,48
    int warp_n = (wid >> 2) * 32;        // 0,32
    int g = t >> 2;                      // 0..7
    int r = t & 3;                       // 0..3

    __shared__ uint32_t As[2][32][72];   // tf32 bits, stride 72 conflict-free
    __shared__ uint32_t Bs[2][32][72];

    int lk = tid >> 4, lq = tid & 15;    // load mapping

    float acc[4][4];
    #pragma unroll
    for (int j = 0; j < 4; j++)
        #pragma unroll
        for (int i = 0; i < 4; i++) acc[j][i] = 0.f;

    float4 ra0, ra1, rb0, rb1;
    // prologue: load chunk 0
    {
        const float* srcA = g_roiT + (size_t)k0 * NROW + row0;
        const float* srcB = g_W2t + (size_t)k0 * CC;
        ra0 = *(const float4*)(srcA + (size_t)lk * NROW + lq * 4);
        ra1 = *(const float4*)(srcA + (size_t)(lk + 16) * NROW + lq * 4);
        rb0 = *(const float4*)(srcB + (size_t)lk * CC + lq * 4);
        rb1 = *(const float4*)(srcB + (size_t)(lk + 16) * CC + lq * 4);
        As[0][lk][lq * 4 + 0] = f2tf32(ra0.x); As[0][lk][lq * 4 + 1] = f2tf32(ra0.y);
        As[0][lk][lq * 4 + 2] = f2tf32(ra0.z); As[0][lk][lq * 4 + 3] = f2tf32(ra0.w);
        As[0][lk + 16][lq * 4 + 0] = f2tf32(ra1.x); As[0][lk + 16][lq * 4 + 1] = f2tf32(ra1.y);
        As[0][lk + 16][lq * 4 + 2] = f2tf32(ra1.z); As[0][lk + 16][lq * 4 + 3] = f2tf32(ra1.w);
        Bs[0][lk][lq * 4 + 0] = f2tf32(rb0.x); Bs[0][lk][lq * 4 + 1] = f2tf32(rb0.y);
        Bs[0][lk][lq * 4 + 2] = f2tf32(rb0.z); Bs[0][lk][lq * 4 + 3] = f2tf32(rb0.w);
        Bs[0][lk + 16][lq * 4 + 0] = f2tf32(rb1.x); Bs[0][lk + 16][lq * 4 + 1] = f2tf32(rb1.y);
        Bs[0][lk + 16][lq * 4 + 2] = f2tf32(rb1.z); Bs[0][lk + 16][lq * 4 + 3] = f2tf32(rb1.w);
    }
    __syncthreads();

    #pragma unroll
    for (int ci = 0; ci < NCHUNK; ci++) {
        int cur = ci & 1, nxt = cur ^ 1;
        if (ci + 1 < NCHUNK) {
            const float* srcA = g_roiT + (size_t)(k0 + (ci + 1) * 32) * NROW + row0;
            const float* srcB = g_W2t + (size_t)(k0 + (ci + 1) * 32) * CC;
            ra0 = *(const float4*)(srcA + (size_t)lk * NROW + lq * 4);
            ra1 = *(const float4*)(srcA + (size_t)(lk + 16) * NROW + lq * 4);
            rb0 = *(const float4*)(srcB + (size_t)lk * CC + lq * 4);
            rb1 = *(const float4*)(srcB + (size_t)(lk + 16) * CC + lq * 4);
        }
        #pragma unroll
        for (int ks = 0; ks < 32; ks += 8) {
            uint32_t a0 = As[cur][ks + r][warp_m + g];
            uint32_t a1 = As[cur][ks + r][warp_m + g + 8];
            uint32_t a2 = As[cur][ks + 4 + r][warp_m + g];
            uint32_t a3 = As[cur][ks + 4 + r][warp_m + g + 8];
            #pragma unroll
            for (int j = 0; j < 4; j++) {
                uint32_t b0 = Bs[cur][ks + r][warp_n + j * 8 + g];
                uint32_t b1 = Bs[cur][ks + 4 + r][warp_n + j * 8 + g];
                asm volatile(
                    "mma.sync.aligned.m16n8k8.row.col.f32.tf32.tf32.f32 "
                    "{%0,%1,%2,%3}, {%4,%5,%6,%7}, {%8,%9}, {%0,%1,%2,%3};"
                    : "+f"(acc[j][0]), "+f"(acc[j][1]),
                      "+f"(acc[j][2]), "+f"(acc[j][3])
                    : "r"(a0), "r"(a1), "r"(a2), "r"(a3),
                      "r"(b0), "r"(b1));
            }
        }
        if (ci + 1 < NCHUNK) {
            As[nxt][lk][lq * 4 + 0] = f2tf32(ra0.x); As[nxt][lk][lq * 4 + 1] = f2tf32(ra0.y);
            As[nxt][lk][lq * 4 + 2] = f2tf32(ra0.z); As[nxt][lk][lq * 4 + 3] = f2tf32(ra0.w);
            As[nxt][lk + 16][lq * 4 + 0] = f2tf32(ra1.x); As[nxt][lk + 16][lq * 4 + 1] = f2tf32(ra1.y);
            As[nxt][lk + 16][lq * 4 + 2] = f2tf32(ra1.z); As[nxt][lk + 16][lq * 4 + 3] = f2tf32(ra1.w);
            Bs[nxt][lk][lq * 4 + 0] = f2tf32(rb0.x); Bs[nxt][lk][lq * 4 + 1] = f2tf32(rb0.y);
            Bs[nxt][lk][lq * 4 + 2] = f2tf32(rb0.z); Bs[nxt][lk][lq * 4 + 3] = f2tf32(rb0.w);
            Bs[nxt][lk + 16][lq * 4 + 0] = f2tf32(rb1.x); Bs[nxt][lk + 16][lq * 4 + 1] = f2tf32(rb1.y);
            Bs[nxt][lk + 16][lq * 4 + 2] = f2tf32(rb1.z); Bs[nxt][lk + 16][lq * 4 + 3] = f2tf32(rb1.w);
            __syncthreads();
        }
    }

    float* outp = &g_xp_part[spl][0];
    #pragma unroll
    for (int j = 0; j < 4; j++) {
        int colb = warp_n + j * 8 + 2 * r;
        int rowa = row0 + warp_m + g;
        *(float2*)&outp[(size_t)rowa * CC + colb] =
            make_float2(acc[j][0], acc[j][1]);
        *(float2*)&outp[(size_t)(rowa + 8) * CC + colb] =
            make_float2(acc[j][2], acc[j][3]);
    }
}

// ---------------- K5: attention (folds split-K reduction) ----------------
__global__ void attn_kernel() {
    extern __shared__ float sm[];
    float* xfs = sm;                      // [64][251]
    float* xps = sm + 64 * 251;           // [16][64]
    float* wbf = xps + 16 * 64;           // [16][250]

    int lq = blockIdx.x;
    int b = blockIdx.y;
    int tid = threadIdx.x;
    int w = tid >> 5, t = tid & 31;
    int lane = lq * 16 + w;
    int n = b * LANES_ + lane;

    for (int i = tid; i < CC * NPOOL; i += 512) {
        int c = i / NPOOL, r = i % NPOOL;
        xfs[c * 251 + r] = g_xf[(b * CC + c) * NPOOL + r];
    }
    for (int o = t; o < CC; o += 32) {
        float s = g_b2[o];
        #pragma unroll
        for (int sp_ = 0; sp_ < NSPLIT; sp_++) s += g_xp_part[sp_][n * CC + o];
        xps[w * CC + o] = s;
    }
    __syncthreads();

    float sc[8];
    float mx = -1e30f;
    #pragma unroll
    for (int j = 0; j < 8; j++) {
        int r = t + 32 * j;
        if (r < NPOOL) {
            float s = 0.f;
            #pragma unroll 8
            for (int c = 0; c < CC; c++) s += xps[w * CC + c] * xfs[c * 251 + r];
            s *= 0.125f;
            sc[j] = s;
            mx = fmaxf(mx, s);
        } else sc[j] = -1e30f;
    }
    #pragma unroll
    for (int off = 16; off > 0; off >>= 1)
        mx = fmaxf(mx, __shfl_xor_sync(0xffffffffu, mx, off));
    float sum = 0.f;
    #pragma unroll
    for (int j = 0; j < 8; j++) { sc[j] = __expf(sc[j] - mx); sum += sc[j]; }
    #pragma unroll
    for (int off = 16; off > 0; off >>= 1)
        sum += __shfl_xor_sync(0xffffffffu, sum, off);
    float inv = 1.0f / sum;
    #pragma unroll
    for (int j = 0; j < 8; j++) {
        int r = t + 32 * j;
        if (r < NPOOL) wbf[w * NPOOL + r] = sc[j] * inv;
    }
    __syncwarp();

    for (int c = t; c < CC; c += 32) {
        float s = 0.f;
        #pragma unroll 10
        for (int r = 0; r < NPOOL; r++) s += wbf[w * NPOOL + r] * xfs[c * 251 + r];
        g_gv[b * (LANES_ * CC) + lane * CC + c] = s;
    }
}

// ---------------- K6: conv1x1 + relu + broadcast-add prior ----------------
__global__ void final_kernel(const float* __restrict__ w1x1,
                             const float* __restrict__ b1x1,
                             const float* __restrict__ prior,
                             float* __restrict__ out) {
    int og = blockIdx.x;
    int b = blockIdx.y;
    int tid = threadIdx.x;
    int w = tid >> 5, t = tid & 31;

    __shared__ float gvs[4096];
    __shared__ float vals[8];
    for (int i = tid; i < 4096; i += 256) gvs[i] = g_gv[b * 4096 + i];
    __syncthreads();

    int o = og * 8 + w;
    const float* wrow = w1x1 + (size_t)o * 4096;
    float s = 0.f;
    for (int j = t * 4; j < 4096; j += 128) {
        float4 wv = *(const float4*)&wrow[j];
        float4 gv = *(const float4*)&gvs[j];
        s += wv.x * gv.x + wv.y * gv.y + wv.z * gv.z + wv.w * gv.w;
    }
    #pragma unroll
    for (int off = 16; off > 0; off >>= 1)
        s += __shfl_xor_sync(0xffffffffu, s, off);
    if (t == 0) vals[w] = fmaxf(s + b1x1[o], 0.f);
    __syncthreads();

    for (int i = tid; i < 8 * PE_; i += 256) {
        int oo = i / PE_, e = i % PE_;
        int oabs = og * 8 + oo;
        int idx = b * (CC * PE_) + oabs * PE_ + e;
        out[idx] = vals[oo] + prior[idx];
    }
}

// ---------------- launch ----------------
extern "C" void kernel_launch(void* const* d_in, const int* in_sizes, int n_in,
                              void* d_out, int out_size) {
    const float* feat    = (const float*)d_in[0];
    const float* prior   = (const float*)d_in[1];
    const float* conv_w  = (const float*)d_in[2];
    const float* conv_b  = (const float*)d_in[3];
    const float* fc_w    = (const float*)d_in[4];
    const float* fc_b    = (const float*)d_in[5];
    const float* w1x1    = (const float*)d_in[6];
    const float* b1x1    = (const float*)d_in[7];
    float* out = (float*)d_out;

    const int pg_smem = (FHH * FWW) * 4 + (SPP * LANES_) * 4 + 16;
    const int attn_smem = (64 * 251 + 16 * 64 + 16 * 250) * (int)sizeof(float);
    cudaFuncSetAttribute(pool_gather_kernel,
                         cudaFuncAttributeMaxDynamicSharedMemorySize, pg_smem);
    cudaFuncSetAttribute(attn_kernel,
                         cudaFuncAttributeMaxDynamicSharedMemorySize, attn_smem);

    w2_kernel<<<dim3(CC, 4), 256>>>(conv_w, conv_b, fc_w, fc_b);
    pool_gather_kernel<<<dim3(CC, BB), 256, pg_smem>>>(feat, prior);
    gemm_kernel<<<dim3(32, NSPLIT), 256>>>();
    attn_kernel<<<dim3(4, BB), 512, attn_smem>>>();
    final_kernel<<<dim3(8, BB), 256>>>(w1x1, b1x1, prior, out);
}

// round 10
// speedup vs baseline: 2.0062x; 1.0135x over previous
#include <cuda_runtime.h>
#include <math.h>
#include <stdint.h>

// ---------------- problem constants ----------------
#define BB     32
#define CC     64
#define FHH    80
#define FWW    200
#define SPP    36
#define LANES_ 64
#define PE_    78
#define RH_    10
#define RW_    25
#define NPOOL  250
#define KDIM   2304          // SPP * CC   (k = s*64 + c)
#define NROW   2048          // B * LANES
#define NSPLIT 12
#define KSPL   192           // KDIM / NSPLIT
#define NCHUNK 6             // KSPL / 32
#define RPAD   260           // padded r-stride for attn smem

// ---------------- device scratch ----------------
__device__ float g_xf[BB * CC * NPOOL];             // pooled features [b][c][r]
__device__ float g_W2t[KDIM * CC];                  // fused weight, k-major [k][o]
__device__ float g_b2[CC];
__device__ float g_roiT[(size_t)KDIM * NROW];       // roi, k-major [k][n]
__device__ float g_xp_part[NSPLIT][NROW * CC];
__device__ float g_gv[BB * LANES_ * CC];

__device__ __forceinline__ uint32_t smem_u32(const void* p) {
    uint32_t a;
    asm("{ .reg .u64 t; cvta.to.shared.u64 t, %1; cvt.u32.u64 %0, t; }"
        : "=r"(a) : "l"(p));
    return a;
}

// ---------------- K1: fused pool + gather (TMA bulk load + xprep inline) ---
__global__ void __launch_bounds__(256) pool_gather_kernel(
        const float* __restrict__ f, const float* __restrict__ prior) {
    extern __shared__ float sm[];
    float* img = sm;                                   // [16000]
    unsigned int* xid = (unsigned int*)(sm + FHH * FWW); // [2304]
    unsigned long long* mbar =
        (unsigned long long*)(sm + FHH * FWW + SPP * LANES_);

    int c = blockIdx.x;
    int b = blockIdx.y;
    int tid = threadIdx.x;

    uint32_t mbar_a = smem_u32(mbar);
    uint32_t img_a  = smem_u32(img);

    if (tid == 0) {
        asm volatile("mbarrier.init.shared.b64 [%0], %1;"
                     :: "r"(mbar_a), "r"(1) : "memory");
    }
    __syncthreads();

    if (tid == 0) {
        const float* src = f + (size_t)(b * CC + c) * (FHH * FWW);
        asm volatile("mbarrier.arrive.expect_tx.shared.b64 _, [%0], %1;"
                     :: "r"(mbar_a), "r"(FHH * FWW * 4) : "memory");
        asm volatile(
            "cp.async.bulk.shared::cluster.global.mbarrier::complete_tx::bytes "
            "[%0], [%1], %2, [%3];"
            :: "r"(img_a), "l"(src), "r"(FHH * FWW * 4), "r"(mbar_a)
            : "memory");
    }

    for (int i = tid; i < SPP * LANES_; i += 256) {
        int sp = i >> 6, lane = i & 63;
        float xv = prior[(b * LANES_ + lane) * PE_ + 6 + 2 * sp] * 0.25f;
        xv = fminf(xv, 199.0f);
        unsigned int xf = (unsigned int)(int)floorf(xv);
        unsigned int xc = (unsigned int)(int)ceilf(xv);
        xid[i] = xf | (xc << 16);
    }

    asm volatile(
        "{\n\t"
        ".reg .pred P;\n\t"
        "W%=:\n\t"
        "mbarrier.try_wait.parity.shared.b64 P, [%0], 0;\n\t"
        "@!P bra W%=;\n\t"
        "}"
        :: "r"(mbar_a) : "memory");
    __syncthreads();

    if (tid < NPOOL) {
        int rh = tid / RW_, rw = tid % RW_;
        const float* base = img + rh * 8 * FWW + rw * 8;
        float s = 0.f;
        #pragma unroll
        for (int rr = 0; rr < 8; rr++) {
            float4 a = *(const float4*)(base + rr * FWW);
            float4 bq = *(const float4*)(base + rr * FWW + 4);
            s += a.x + a.y + a.z + a.w + bq.x + bq.y + bq.z + bq.w;
        }
        g_xf[(size_t)(b * CC + c) * NPOOL + tid] = s * (1.0f / 64.0f);
    }

    #pragma unroll
    for (int it = 0; it < 9; it++) {
        int i = tid + it * 256;
        int sp = i >> 6, lane = i & 63;
        float yv = 0.25f * (319.0f - (320.0f / 71.0f) * (float)(2 * sp));
        yv = fminf(yv, 79.0f);
        int yf = (int)floorf(yv);
        int yc = (int)ceilf(yv);
        unsigned int p = xid[i];
        int xf = (int)(p & 0xffffu), xc = (int)(p >> 16);
        const float* rA = img + yf * FWW;
        const float* rB = img + yc * FWW;
        float v = rA[xf] + rA[xc] + rB[xf] + rB[xc];
        g_roiT[(size_t)(sp * CC + c) * NROW + b * LANES_ + lane] = 0.25f * v;
    }
}

// ---------------- K2: fuse conv1d + fc into W2t / b2 ----------------
__global__ void w2_kernel(const float* __restrict__ conv_w,
                          const float* __restrict__ conv_b,
                          const float* __restrict__ fc_w,
                          const float* __restrict__ fc_b) {
    int o = blockIdx.x;      // 0..63
    int q = blockIdx.y;      // 0..3 (c1 group of 16)
    int tid = threadIdx.x;
    __shared__ float fcrow[2048];
    __shared__ float convs[64 * 16 * 5];     // [c2][c1l][k]
    __shared__ float bpart[64];

    for (int i = tid; i < 2048; i += 256) fcrow[i] = fc_w[o * 2048 + i];
    for (int i = tid; i < 5120; i += 256) {
        int c2 = i / 80, rem = i % 80;
        int c1l = rem / 5, k = rem % 5;
        convs[i] = conv_w[(c2 * CC + q * 16 + c1l) * 5 + k];
    }
    __syncthreads();

    for (int i = tid; i < 16 * SPP; i += 256) {
        int c1l = i / SPP, s = i % SPP;
        float acc = 0.f;
        for (int c2 = 0; c2 < CC; c2++) {
            const float* w5 = &convs[c2 * 80 + c1l * 5];
            const float* fr = &fcrow[c2 * 32];
            #pragma unroll
            for (int k = 0; k < 5; k++) {
                int p = s - k;
                if (p >= 0 && p < 32) acc += w5[k] * fr[p];
            }
        }
        g_W2t[(size_t)(s * CC + q * 16 + c1l) * CC + o] = acc;
    }

    if (q == 0) {
        if (tid < CC) {
            float s = 0.f;
            #pragma unroll
            for (int p = 0; p < 32; p++) s += fcrow[tid * 32 + p];
            bpart[tid] = s * conv_b[tid];
        }
        __syncthreads();
        if (tid == 0) {
            float s = fc_b[o];
            for (int j = 0; j < CC; j++) s += bpart[j];
            g_b2[o] = s;
        }
    }
}

// ---------------- K4: tf32 tensor-core GEMM, K-split, double-buffered ------
__device__ __forceinline__ uint32_t f2tf32(float x) {
    uint32_t u;
    asm("cvt.rna.tf32.f32 %0, %1;" : "=r"(u) : "f"(x));
    return u;
}

__global__ void __launch_bounds__(256) gemm_kernel() {
    int mblk = blockIdx.x;
    int spl  = blockIdx.y;
    int tid = threadIdx.x;
    int wid = tid >> 5;
    int t = tid & 31;
    int row0 = mblk * 64;
    int k0 = spl * KSPL;

    int warp_m = (wid & 3) * 16;
    int warp_n = (wid >> 2) * 32;
    int g = t >> 2;
    int r = t & 3;

    __shared__ uint32_t As[2][32][72];
    __shared__ uint32_t Bs[2][32][72];

    int lk = tid >> 4, lq = tid & 15;

    float acc[4][4];
    #pragma unroll
    for (int j = 0; j < 4; j++)
        #pragma unroll
        for (int i = 0; i < 4; i++) acc[j][i] = 0.f;

    float4 ra0, ra1, rb0, rb1;
    {
        const float* srcA = g_roiT + (size_t)k0 * NROW + row0;
        const float* srcB = g_W2t + (size_t)k0 * CC;
        ra0 = *(const float4*)(srcA + (size_t)lk * NROW + lq * 4);
        ra1 = *(const float4*)(srcA + (size_t)(lk + 16) * NROW + lq * 4);
        rb0 = *(const float4*)(srcB + (size_t)lk * CC + lq * 4);
        rb1 = *(const float4*)(srcB + (size_t)(lk + 16) * CC + lq * 4);
        As[0][lk][lq * 4 + 0] = f2tf32(ra0.x); As[0][lk][lq * 4 + 1] = f2tf32(ra0.y);
        As[0][lk][lq * 4 + 2] = f2tf32(ra0.z); As[0][lk][lq * 4 + 3] = f2tf32(ra0.w);
        As[0][lk + 16][lq * 4 + 0] = f2tf32(ra1.x); As[0][lk + 16][lq * 4 + 1] = f2tf32(ra1.y);
        As[0][lk + 16][lq * 4 + 2] = f2tf32(ra1.z); As[0][lk + 16][lq * 4 + 3] = f2tf32(ra1.w);
        Bs[0][lk][lq * 4 + 0] = f2tf32(rb0.x); Bs[0][lk][lq * 4 + 1] = f2tf32(rb0.y);
        Bs[0][lk][lq * 4 + 2] = f2tf32(rb0.z); Bs[0][lk][lq * 4 + 3] = f2tf32(rb0.w);
        Bs[0][lk + 16][lq * 4 + 0] = f2tf32(rb1.x); Bs[0][lk + 16][lq * 4 + 1] = f2tf32(rb1.y);
        Bs[0][lk + 16][lq * 4 + 2] = f2tf32(rb1.z); Bs[0][lk + 16][lq * 4 + 3] = f2tf32(rb1.w);
    }
    __syncthreads();

    #pragma unroll
    for (int ci = 0; ci < NCHUNK; ci++) {
        int cur = ci & 1, nxt = cur ^ 1;
        if (ci + 1 < NCHUNK) {
            const float* srcA = g_roiT + (size_t)(k0 + (ci + 1) * 32) * NROW + row0;
            const float* srcB = g_W2t + (size_t)(k0 + (ci + 1) * 32) * CC;
            ra0 = *(const float4*)(srcA + (size_t)lk * NROW + lq * 4);
            ra1 = *(const float4*)(srcA + (size_t)(lk + 16) * NROW + lq * 4);
            rb0 = *(const float4*)(srcB + (size_t)lk * CC + lq * 4);
            rb1 = *(const float4*)(srcB + (size_t)(lk + 16) * CC + lq * 4);
        }
        #pragma unroll
        for (int ks = 0; ks < 32; ks += 8) {
            uint32_t a0 = As[cur][ks + r][warp_m + g];
            uint32_t a1 = As[cur][ks + r][warp_m + g + 8];
            uint32_t a2 = As[cur][ks + 4 + r][warp_m + g];
            uint32_t a3 = As[cur][ks + 4 + r][warp_m + g + 8];
            #pragma unroll
            for (int j = 0; j < 4; j++) {
                uint32_t b0 = Bs[cur][ks + r][warp_n + j * 8 + g];
                uint32_t b1 = Bs[cur][ks + 4 + r][warp_n + j * 8 + g];
                asm volatile(
                    "mma.sync.aligned.m16n8k8.row.col.f32.tf32.tf32.f32 "
                    "{%0,%1,%2,%3}, {%4,%5,%6,%7}, {%8,%9}, {%0,%1,%2,%3};"
                    : "+f"(acc[j][0]), "+f"(acc[j][1]),
                      "+f"(acc[j][2]), "+f"(acc[j][3])
                    : "r"(a0), "r"(a1), "r"(a2), "r"(a3),
                      "r"(b0), "r"(b1));
            }
        }
        if (ci + 1 < NCHUNK) {
            As[nxt][lk][lq * 4 + 0] = f2tf32(ra0.x); As[nxt][lk][lq * 4 + 1] = f2tf32(ra0.y);
            As[nxt][lk][lq * 4 + 2] = f2tf32(ra0.z); As[nxt][lk][lq * 4 + 3] = f2tf32(ra0.w);
            As[nxt][lk + 16][lq * 4 + 0] = f2tf32(ra1.x); As[nxt][lk + 16][lq * 4 + 1] = f2tf32(ra1.y);
            As[nxt][lk + 16][lq * 4 + 2] = f2tf32(ra1.z); As[nxt][lk + 16][lq * 4 + 3] = f2tf32(ra1.w);
            Bs[nxt][lk][lq * 4 + 0] = f2tf32(rb0.x); Bs[nxt][lk][lq * 4 + 1] = f2tf32(rb0.y);
            Bs[nxt][lk][lq * 4 + 2] = f2tf32(rb0.z); Bs[nxt][lk][lq * 4 + 3] = f2tf32(rb0.w);
            Bs[nxt][lk + 16][lq * 4 + 0] = f2tf32(rb1.x); Bs[nxt][lk + 16][lq * 4 + 1] = f2tf32(rb1.y);
            Bs[nxt][lk + 16][lq * 4 + 2] = f2tf32(rb1.z); Bs[nxt][lk + 16][lq * 4 + 3] = f2tf32(rb1.w);
            __syncthreads();
        }
    }

    float* outp = &g_xp_part[spl][0];
    #pragma unroll
    for (int j = 0; j < 4; j++) {
        int colb = warp_n + j * 8 + 2 * r;
        int rowa = row0 + warp_m + g;
        *(float2*)&outp[(size_t)rowa * CC + colb] =
            make_float2(acc[j][0], acc[j][1]);
        *(float2*)&outp[(size_t)(rowa + 8) * CC + colb] =
            make_float2(acc[j][2], acc[j][3]);
    }
}

// ---------------- K5: attention v2 (vectorized, 256 blocks) ----------------
// block = (lq 0..7, b). 8 warps, one lane each: lane = lq*8 + w.
// smem: xfs[64][RPAD] zero-padded, wbf[8][RPAD], xps[8][64].
__global__ void __launch_bounds__(256) attn_kernel() {
    extern __shared__ float sm[];
    float* xfs = sm;                          // [64][RPAD]
    float* wbf = sm + CC * RPAD;              // [8][RPAD]
    float* xps = wbf + 8 * RPAD;              // [8][64]

    int lq = blockIdx.x;                      // 0..7
    int b = blockIdx.y;
    int tid = threadIdx.x;
    int w = tid >> 5, t = tid & 31;
    int lane = lq * 8 + w;
    int n = b * LANES_ + lane;

    // load x_f, zero-padding r in [250, RPAD)
    for (int i = tid; i < CC * RPAD; i += 256) {
        int c = i / RPAD, r = i % RPAD;
        xfs[i] = (r < NPOOL) ? g_xf[(size_t)(b * CC + c) * NPOOL + r] : 0.f;
    }
    // x_p: reduce split partials + bias (2 outputs per thread)
    {
        const float* bp = &g_xp_part[0][0];
        #pragma unroll 2
        for (int jj = 0; jj < 2; jj++) {
            int o = t + jj * 32;
            float s = g_b2[o];
            #pragma unroll
            for (int sp_ = 0; sp_ < NSPLIT; sp_++)
                s += bp[(size_t)sp_ * (NROW * CC) + n * CC + o];
            xps[w * CC + o] = s;
        }
    }
    __syncthreads();

    // scores: thread owns r-quads q = t and t+32 (covers r 0..255; pads masked)
    float4 s0 = make_float4(0.f, 0.f, 0.f, 0.f);
    float4 s1 = make_float4(0.f, 0.f, 0.f, 0.f);
    {
        const float* xp = &xps[w * CC];
        #pragma unroll 8
        for (int c = 0; c < CC; c++) {
            float xv = xp[c];
            float4 f0 = *(const float4*)&xfs[c * RPAD + 4 * t];
            float4 f1 = *(const float4*)&xfs[c * RPAD + 4 * t + 128];
            s0.x += xv * f0.x; s0.y += xv * f0.y;
            s0.z += xv * f0.z; s0.w += xv * f0.w;
            s1.x += xv * f1.x; s1.y += xv * f1.y;
            s1.z += xv * f1.z; s1.w += xv * f1.w;
        }
    }
    float sc[8] = {s0.x, s0.y, s0.z, s0.w, s1.x, s1.y, s1.z, s1.w};
    float mx = -1e30f;
    #pragma unroll
    for (int j = 0; j < 8; j++) {
        int r = (j < 4) ? (4 * t + j) : (4 * t + 128 + (j - 4));
        sc[j] = (r < NPOOL) ? sc[j] * 0.125f : -1e30f;
        mx = fmaxf(mx, sc[j]);
    }
    #pragma unroll
    for (int off = 16; off > 0; off >>= 1)
        mx = fmaxf(mx, __shfl_xor_sync(0xffffffffu, mx, off));
    float sum = 0.f;
    #pragma unroll
    for (int j = 0; j < 8; j++) { sc[j] = __expf(sc[j] - mx); sum += sc[j]; }
    #pragma unroll
    for (int off = 16; off > 0; off >>= 1)
        sum += __shfl_xor_sync(0xffffffffu, sum, off);
    float inv = 1.0f / sum;
    {
        float* wr = &wbf[w * RPAD];
        *(float4*)&wr[4 * t] =
            make_float4(sc[0] * inv, sc[1] * inv, sc[2] * inv, sc[3] * inv);
        *(float4*)&wr[4 * t + 128] =
            make_float4(sc[4] * inv, sc[5] * inv, sc[6] * inv, sc[7] * inv);
    }
    __syncwarp();

    // g[c] = sum_r w[r]*xf[c][r]; thread owns c = t, t+32; r in quads 0..63
    {
        const float* wr = &wbf[w * RPAD];
        float a0 = 0.f, a1 = 0.f;
        #pragma unroll 8
        for (int q = 0; q < 64; q++) {
            float4 wv = *(const float4*)&wr[4 * q];
            float4 f0 = *(const float4*)&xfs[t * RPAD + 4 * q];
            float4 f1 = *(const float4*)&xfs[(t + 32) * RPAD + 4 * q];
            a0 += wv.x * f0.x + wv.y * f0.y + wv.z * f0.z + wv.w * f0.w;
            a1 += wv.x * f1.x + wv.y * f1.y + wv.z * f1.z + wv.w * f1.w;
        }
        g_gv[b * (LANES_ * CC) + lane * CC + t] = a0;
        g_gv[b * (LANES_ * CC) + lane * CC + t + 32] = a1;
    }
}

// ---------------- K6: conv1x1 + relu + broadcast-add prior ----------------
__global__ void final_kernel(const float* __restrict__ w1x1,
                             const float* __restrict__ b1x1,
                             const float* __restrict__ prior,
                             float* __restrict__ out) {
    int og = blockIdx.x;
    int b = blockIdx.y;
    int tid = threadIdx.x;
    int w = tid >> 5, t = tid & 31;

    __shared__ float gvs[4096];
    __shared__ float vals[8];
    for (int i = tid; i < 4096; i += 256) gvs[i] = g_gv[b * 4096 + i];
    __syncthreads();

    int o = og * 8 + w;
    const float* wrow = w1x1 + (size_t)o * 4096;
    float s = 0.f;
    for (int j = t * 4; j < 4096; j += 128) {
        float4 wv = *(const float4*)&wrow[j];
        float4 gv = *(const float4*)&gvs[j];
        s += wv.x * gv.x + wv.y * gv.y + wv.z * gv.z + wv.w * gv.w;
    }
    #pragma unroll
    for (int off = 16; off > 0; off >>= 1)
        s += __shfl_xor_sync(0xffffffffu, s, off);
    if (t == 0) vals[w] = fmaxf(s + b1x1[o], 0.f);
    __syncthreads();

    for (int i = tid; i < 8 * PE_; i += 256) {
        int oo = i / PE_, e = i % PE_;
        int oabs = og * 8 + oo;
        int idx = b * (CC * PE_) + oabs * PE_ + e;
        out[idx] = vals[oo] + prior[idx];
    }
}

// ---------------- launch ----------------
extern "C" void kernel_launch(void* const* d_in, const int* in_sizes, int n_in,
                              void* d_out, int out_size) {
    const float* feat    = (const float*)d_in[0];
    const float* prior   = (const float*)d_in[1];
    const float* conv_w  = (const float*)d_in[2];
    const float* conv_b  = (const float*)d_in[3];
    const float* fc_w    = (const float*)d_in[4];
    const float* fc_b    = (const float*)d_in[5];
    const float* w1x1    = (const float*)d_in[6];
    const float* b1x1    = (const float*)d_in[7];
    float* out = (float*)d_out;

    const int pg_smem = (FHH * FWW) * 4 + (SPP * LANES_) * 4 + 16;
    const int attn_smem = (CC * RPAD + 8 * RPAD + 8 * CC) * (int)sizeof(float);
    cudaFuncSetAttribute(pool_gather_kernel,
                         cudaFuncAttributeMaxDynamicSharedMemorySize, pg_smem);
    cudaFuncSetAttribute(attn_kernel,
                         cudaFuncAttributeMaxDynamicSharedMemorySize, attn_smem);

    w2_kernel<<<dim3(CC, 4), 256>>>(conv_w, conv_b, fc_w, fc_b);
    pool_gather_kernel<<<dim3(CC, BB), 256, pg_smem>>>(feat, prior);
    gemm_kernel<<<dim3(32, NSPLIT), 256>>>();
    attn_kernel<<<dim3(8, BB), 256, attn_smem>>>();
    final_kernel<<<dim3(8, BB), 256>>>(w1x1, b1x1, prior, out);
}

// round 11
// speedup vs baseline: 2.5575x; 1.2748x over previous
#include <cuda_runtime.h>
#include <cuda_bf16.h>
#include <math.h>
#include <stdint.h>

// ---------------- problem constants ----------------
#define BB     32
#define CC     64
#define FHH    80
#define FWW    200
#define SPP    36
#define LANES_ 64
#define PE_    78
#define RH_    10
#define RW_    25
#define NPOOL  250
#define KDIM   2304          // SPP * CC   (k = s*64 + c)
#define NROW   2048          // B * LANES
#define NSPLIT 12
#define KSPL   192           // KDIM / NSPLIT
#define NCHUNK 6             // KSPL / 32
#define RPADH  264           // bf16 r-stride in attn smem (528B rows)

// ---------------- device scratch ----------------
__device__ float g_xf[BB * CC * NPOOL];             // pooled features [b][c][r]
__device__ float g_W2t[KDIM * CC];                  // fused weight, k-major [k][o]
__device__ float g_b2[CC];
__device__ float g_roiT[(size_t)KDIM * NROW];       // roi, k-major [k][n]
__device__ float g_xp_part[NSPLIT][NROW * CC];
__device__ float g_gv[BB * LANES_ * CC];

__device__ __forceinline__ uint32_t smem_u32(const void* p) {
    uint32_t a;
    asm("{ .reg .u64 t; cvta.to.shared.u64 t, %1; cvt.u32.u64 %0, t; }"
        : "=r"(a) : "l"(p));
    return a;
}

// ---------------- pg part: TMA pool+gather (per channel-image) -------------
__device__ __forceinline__ void pg_body(
        const float* __restrict__ f, const float* __restrict__ prior,
        int c, int b, float* sm) {
    float* img = sm;                                   // [16000]
    unsigned int* xid = (unsigned int*)(sm + FHH * FWW); // [2304]
    unsigned long long* mbar =
        (unsigned long long*)(sm + FHH * FWW + SPP * LANES_);
    int tid = threadIdx.x;

    uint32_t mbar_a = smem_u32(mbar);
    uint32_t img_a  = smem_u32(img);

    if (tid == 0) {
        asm volatile("mbarrier.init.shared.b64 [%0], %1;"
                     :: "r"(mbar_a), "r"(1) : "memory");
    }
    __syncthreads();

    if (tid == 0) {
        const float* src = f + (size_t)(b * CC + c) * (FHH * FWW);
        asm volatile("mbarrier.arrive.expect_tx.shared.b64 _, [%0], %1;"
                     :: "r"(mbar_a), "r"(FHH * FWW * 4) : "memory");
        asm volatile(
            "cp.async.bulk.shared::cluster.global.mbarrier::complete_tx::bytes "
            "[%0], [%1], %2, [%3];"
            :: "r"(img_a), "l"(src), "r"(FHH * FWW * 4), "r"(mbar_a)
            : "memory");
    }

    for (int i = tid; i < SPP * LANES_; i += 256) {
        int sp = i >> 6, lane = i & 63;
        float xv = prior[(b * LANES_ + lane) * PE_ + 6 + 2 * sp] * 0.25f;
        xv = fminf(xv, 199.0f);
        unsigned int xf = (unsigned int)(int)floorf(xv);
        unsigned int xc = (unsigned int)(int)ceilf(xv);
        xid[i] = xf | (xc << 16);
    }

    asm volatile(
        "{\n\t"
        ".reg .pred P;\n\t"
        "W%=:\n\t"
        "mbarrier.try_wait.parity.shared.b64 P, [%0], 0;\n\t"
        "@!P bra W%=;\n\t"
        "}"
        :: "r"(mbar_a) : "memory");
    __syncthreads();

    if (tid < NPOOL) {
        int rh = tid / RW_, rw = tid % RW_;
        const float* base = img + rh * 8 * FWW + rw * 8;
        float s = 0.f;
        #pragma unroll
        for (int rr = 0; rr < 8; rr++) {
            float4 a = *(const float4*)(base + rr * FWW);
            float4 bq = *(const float4*)(base + rr * FWW + 4);
            s += a.x + a.y + a.z + a.w + bq.x + bq.y + bq.z + bq.w;
        }
        g_xf[(size_t)(b * CC + c) * NPOOL + tid] = s * (1.0f / 64.0f);
    }

    #pragma unroll
    for (int it = 0; it < 9; it++) {
        int i = tid + it * 256;
        int sp = i >> 6, lane = i & 63;
        float yv = 0.25f * (319.0f - (320.0f / 71.0f) * (float)(2 * sp));
        yv = fminf(yv, 79.0f);
        int yf = (int)floorf(yv);
        int yc = (int)ceilf(yv);
        unsigned int p = xid[i];
        int xf = (int)(p & 0xffffu), xc = (int)(p >> 16);
        const float* rA = img + yf * FWW;
        const float* rB = img + yc * FWW;
        float v = rA[xf] + rA[xc] + rB[xf] + rB[xc];
        g_roiT[(size_t)(sp * CC + c) * NROW + b * LANES_ + lane] = 0.25f * v;
    }
}

// ---------------- w2 part: fuse conv1d + fc into W2t / b2 ------------------
__device__ __forceinline__ void w2_body(
        const float* __restrict__ conv_w, const float* __restrict__ conv_b,
        const float* __restrict__ fc_w,   const float* __restrict__ fc_b,
        int o, int q, float* sm) {
    float* fcrow = sm;            // [2048]
    float* convs = sm + 2048;     // [5120]  [c2][c1l][k]
    float* bpart = sm + 7168;     // [64]
    int tid = threadIdx.x;

    for (int i = tid; i < 2048; i += 256) fcrow[i] = fc_w[o * 2048 + i];
    for (int i = tid; i < 5120; i += 256) {
        int c2 = i / 80, rem = i % 80;
        int c1l = rem / 5, k = rem % 5;
        convs[i] = conv_w[(c2 * CC + q * 16 + c1l) * 5 + k];
    }
    __syncthreads();

    for (int i = tid; i < 16 * SPP; i += 256) {
        int c1l = i / SPP, s = i % SPP;
        float acc = 0.f;
        for (int c2 = 0; c2 < CC; c2++) {
            const float* w5 = &convs[c2 * 80 + c1l * 5];
            const float* fr = &fcrow[c2 * 32];
            #pragma unroll
            for (int k = 0; k < 5; k++) {
                int p = s - k;
                if (p >= 0 && p < 32) acc += w5[k] * fr[p];
            }
        }
        g_W2t[(size_t)(s * CC + q * 16 + c1l) * CC + o] = acc;
    }

    if (q == 0) {
        if (tid < CC) {
            float s = 0.f;
            #pragma unroll
            for (int p = 0; p < 32; p++) s += fcrow[tid * 32 + p];
            bpart[tid] = s * conv_b[tid];
        }
        __syncthreads();
        if (tid == 0) {
            float s = fc_b[o];
            for (int j = 0; j < CC; j++) s += bpart[j];
            g_b2[o] = s;
        }
    }
}

// ---------------- K1: merged prep (w2 blocks first, then pg blocks) --------
__global__ void __launch_bounds__(256) prep_kernel(
        const float* __restrict__ f, const float* __restrict__ prior,
        const float* __restrict__ conv_w, const float* __restrict__ conv_b,
        const float* __restrict__ fc_w,   const float* __restrict__ fc_b) {
    extern __shared__ float sm[];
    int bid = blockIdx.x;
    if (bid < 256) {
        w2_body(conv_w, conv_b, fc_w, fc_b, bid >> 2, bid & 3, sm);
    } else {
        int idx = bid - 256;
        pg_body(f, prior, idx & 63, idx >> 6, sm);
    }
}

// ---------------- K2: tf32 tensor-core GEMM, K-split, double-buffered ------
__device__ __forceinline__ uint32_t f2tf32(float x) {
    uint32_t u;
    asm("cvt.rna.tf32.f32 %0, %1;" : "=r"(u) : "f"(x));
    return u;
}

__global__ void __launch_bounds__(256) gemm_kernel() {
    int mblk = blockIdx.x;
    int spl  = blockIdx.y;
    int tid = threadIdx.x;
    int wid = tid >> 5;
    int t = tid & 31;
    int row0 = mblk * 64;
    int k0 = spl * KSPL;

    int warp_m = (wid & 3) * 16;
    int warp_n = (wid >> 2) * 32;
    int g = t >> 2;
    int r = t & 3;

    __shared__ uint32_t As[2][32][72];
    __shared__ uint32_t Bs[2][32][72];

    int lk = tid >> 4, lq = tid & 15;

    float acc[4][4];
    #pragma unroll
    for (int j = 0; j < 4; j++)
        #pragma unroll
        for (int i = 0; i < 4; i++) acc[j][i] = 0.f;

    float4 ra0, ra1, rb0, rb1;
    {
        const float* srcA = g_roiT + (size_t)k0 * NROW + row0;
        const float* srcB = g_W2t + (size_t)k0 * CC;
        ra0 = *(const float4*)(srcA + (size_t)lk * NROW + lq * 4);
        ra1 = *(const float4*)(srcA + (size_t)(lk + 16) * NROW + lq * 4);
        rb0 = *(const float4*)(srcB + (size_t)lk * CC + lq * 4);
        rb1 = *(const float4*)(srcB + (size_t)(lk + 16) * CC + lq * 4);
        As[0][lk][lq * 4 + 0] = f2tf32(ra0.x); As[0][lk][lq * 4 + 1] = f2tf32(ra0.y);
        As[0][lk][lq * 4 + 2] = f2tf32(ra0.z); As[0][lk][lq * 4 + 3] = f2tf32(ra0.w);
        As[0][lk + 16][lq * 4 + 0] = f2tf32(ra1.x); As[0][lk + 16][lq * 4 + 1] = f2tf32(ra1.y);
        As[0][lk + 16][lq * 4 + 2] = f2tf32(ra1.z); As[0][lk + 16][lq * 4 + 3] = f2tf32(ra1.w);
        Bs[0][lk][lq * 4 + 0] = f2tf32(rb0.x); Bs[0][lk][lq * 4 + 1] = f2tf32(rb0.y);
        Bs[0][lk][lq * 4 + 2] = f2tf32(rb0.z); Bs[0][lk][lq * 4 + 3] = f2tf32(rb0.w);
        Bs[0][lk + 16][lq * 4 + 0] = f2tf32(rb1.x); Bs[0][lk + 16][lq * 4 + 1] = f2tf32(rb1.y);
        Bs[0][lk + 16][lq * 4 + 2] = f2tf32(rb1.z); Bs[0][lk + 16][lq * 4 + 3] = f2tf32(rb1.w);
    }
    __syncthreads();

    #pragma unroll
    for (int ci = 0; ci < NCHUNK; ci++) {
        int cur = ci & 1, nxt = cur ^ 1;
        if (ci + 1 < NCHUNK) {
            const float* srcA = g_roiT + (size_t)(k0 + (ci + 1) * 32) * NROW + row0;
            const float* srcB = g_W2t + (size_t)(k0 + (ci + 1) * 32) * CC;
            ra0 = *(const float4*)(srcA + (size_t)lk * NROW + lq * 4);
            ra1 = *(const float4*)(srcA + (size_t)(lk + 16) * NROW + lq * 4);
            rb0 = *(const float4*)(srcB + (size_t)lk * CC + lq * 4);
            rb1 = *(const float4*)(srcB + (size_t)(lk + 16) * CC + lq * 4);
        }
        #pragma unroll
        for (int ks = 0; ks < 32; ks += 8) {
            uint32_t a0 = As[cur][ks + r][warp_m + g];
            uint32_t a1 = As[cur][ks + r][warp_m + g + 8];
            uint32_t a2 = As[cur][ks + 4 + r][warp_m + g];
            uint32_t a3 = As[cur][ks + 4 + r][warp_m + g + 8];
            #pragma unroll
            for (int j = 0; j < 4; j++) {
                uint32_t b0 = Bs[cur][ks + r][warp_n + j * 8 + g];
                uint32_t b1 = Bs[cur][ks + 4 + r][warp_n + j * 8 + g];
                asm volatile(
                    "mma.sync.aligned.m16n8k8.row.col.f32.tf32.tf32.f32 "
                    "{%0,%1,%2,%3}, {%4,%5,%6,%7}, {%8,%9}, {%0,%1,%2,%3};"
                    : "+f"(acc[j][0]), "+f"(acc[j][1]),
                      "+f"(acc[j][2]), "+f"(acc[j][3])
                    : "r"(a0), "r"(a1), "r"(a2), "r"(a3),
                      "r"(b0), "r"(b1));
            }
        }
        if (ci + 1 < NCHUNK) {
            As[nxt][lk][lq * 4 + 0] = f2tf32(ra0.x); As[nxt][lk][lq * 4 + 1] = f2tf32(ra0.y);
            As[nxt][lk][lq * 4 + 2] = f2tf32(ra0.z); As[nxt][lk][lq * 4 + 3] = f2tf32(ra0.w);
            As[nxt][lk + 16][lq * 4 + 0] = f2tf32(ra1.x); As[nxt][lk + 16][lq * 4 + 1] = f2tf32(ra1.y);
            As[nxt][lk + 16][lq * 4 + 2] = f2tf32(ra1.z); As[nxt][lk + 16][lq * 4 + 3] = f2tf32(ra1.w);
            Bs[nxt][lk][lq * 4 + 0] = f2tf32(rb0.x); Bs[nxt][lk][lq * 4 + 1] = f2tf32(rb0.y);
            Bs[nxt][lk][lq * 4 + 2] = f2tf32(rb0.z); Bs[nxt][lk][lq * 4 + 3] = f2tf32(rb0.w);
            Bs[nxt][lk + 16][lq * 4 + 0] = f2tf32(rb1.x); Bs[nxt][lk + 16][lq * 4 + 1] = f2tf32(rb1.y);
            Bs[nxt][lk + 16][lq * 4 + 2] = f2tf32(rb1.z); Bs[nxt][lk + 16][lq * 4 + 3] = f2tf32(rb1.w);
            __syncthreads();
        }
    }

    float* outp = &g_xp_part[spl][0];
    #pragma unroll
    for (int j = 0; j < 4; j++) {
        int colb = warp_n + j * 8 + 2 * r;
        int rowa = row0 + warp_m + g;
        *(float2*)&outp[(size_t)rowa * CC + colb] =
            make_float2(acc[j][0], acc[j][1]);
        *(float2*)&outp[(size_t)(rowa + 8) * CC + colb] =
            make_float2(acc[j][2], acc[j][3]);
    }
}

// ---------------- K3: attention v3 (bf16 xfs, 44KB smem, 5 blocks/SM) ------
// block = (lq 0..7, b). 8 warps, one lane each: lane = lq*8 + w.
__global__ void __launch_bounds__(256) attn_kernel() {
    extern __shared__ float smf[];
    __nv_bfloat16* xfs = (__nv_bfloat16*)smf;        // [64][RPADH] bf16
    float* wbf = smf + (CC * RPADH) / 2;             // [8][260]
    float* xps = wbf + 8 * 260;                      // [8][64]

    int lq = blockIdx.x;                             // 0..7
    int b = blockIdx.y;
    int tid = threadIdx.x;
    int w = tid >> 5, t = tid & 31;
    int lane = lq * 8 + w;
    int n = b * LANES_ + lane;

    // load x_f (fp32 global -> bf16 smem), zero-pad r in [250, RPADH)
    {
        const float* src = &g_xf[(size_t)b * (CC * NPOOL)];
        for (int i = tid; i < CC * NPOOL; i += 256) {
            int c = i / NPOOL, r = i % NPOOL;
            xfs[c * RPADH + r] = __float2bfloat16_rn(src[i]);
        }
        for (int i = tid; i < CC * (RPADH - NPOOL); i += 256) {
            int c = i / (RPADH - NPOOL), r = NPOOL + i % (RPADH - NPOOL);
            xfs[c * RPADH + r] = __float2bfloat16_rn(0.f);
        }
    }
    // x_p: reduce split partials + bias
    {
        const float* bp = &g_xp_part[0][0];
        #pragma unroll 2
        for (int jj = 0; jj < 2; jj++) {
            int o = t + jj * 32;
            float s = g_b2[o];
            #pragma unroll
            for (int sp_ = 0; sp_ < NSPLIT; sp_++)
                s += bp[(size_t)sp_ * (NROW * CC) + n * CC + o];
            xps[w * CC + o] = s;
        }
    }
    __syncthreads();

    // scores: thread t owns r = 8t..8t+7
    float sc[8];
    #pragma unroll
    for (int j = 0; j < 8; j++) sc[j] = 0.f;
    {
        const float* xp = &xps[w * CC];
        #pragma unroll 4
        for (int c = 0; c < CC; c++) {
            float xv = xp[c];
            uint4 v = ((const uint4*)(xfs + c * RPADH))[t];
            float2 f0 = __bfloat1622float2(*(__nv_bfloat162*)&v.x);
            float2 f1 = __bfloat1622float2(*(__nv_bfloat162*)&v.y);
            float2 f2 = __bfloat1622float2(*(__nv_bfloat162*)&v.z);
            float2 f3 = __bfloat1622float2(*(__nv_bfloat162*)&v.w);
            sc[0] += xv * f0.x; sc[1] += xv * f0.y;
            sc[2] += xv * f1.x; sc[3] += xv * f1.y;
            sc[4] += xv * f2.x; sc[5] += xv * f2.y;
            sc[6] += xv * f3.x; sc[7] += xv * f3.y;
        }
    }
    float mx = -1e30f;
    #pragma unroll
    for (int j = 0; j < 8; j++) {
        int r = 8 * t + j;
        sc[j] = (r < NPOOL) ? sc[j] * 0.125f : -1e30f;
        mx = fmaxf(mx, sc[j]);
    }
    #pragma unroll
    for (int off = 16; off > 0; off >>= 1)
        mx = fmaxf(mx, __shfl_xor_sync(0xffffffffu, mx, off));
    float sum = 0.f;
    #pragma unroll
    for (int j = 0; j < 8; j++) { sc[j] = __expf(sc[j] - mx); sum += sc[j]; }
    #pragma unroll
    for (int off = 16; off > 0; off >>= 1)
        sum += __shfl_xor_sync(0xffffffffu, sum, off);
    float inv = 1.0f / sum;
    {
        float* wr = &wbf[w * 260];
        *(float4*)&wr[8 * t] =
            make_float4(sc[0] * inv, sc[1] * inv, sc[2] * inv, sc[3] * inv);
        *(float4*)&wr[8 * t + 4] =
            make_float4(sc[4] * inv, sc[5] * inv, sc[6] * inv, sc[7] * inv);
    }
    __syncwarp();

    // g[c] = sum_r w[r]*xf[c][r]; thread owns c = t, t+32
    {
        const float* wr = &wbf[w * 260];
        float a0 = 0.f, a1 = 0.f;
        #pragma unroll 4
        for (int q = 0; q < 32; q++) {
            float4 w0 = *(const float4*)&wr[8 * q];
            float4 w1 = *(const float4*)&wr[8 * q + 4];
            uint4 v0 = ((const uint4*)(xfs + t * RPADH))[q];
            uint4 v1 = ((const uint4*)(xfs + (t + 32) * RPADH))[q];
            float2 p;
            p = __bfloat1622float2(*(__nv_bfloat162*)&v0.x); a0 += w0.x * p.x + w0.y * p.y;
            p = __bfloat1622float2(*(__nv_bfloat162*)&v0.y); a0 += w0.z * p.x + w0.w * p.y;
            p = __bfloat1622float2(*(__nv_bfloat162*)&v0.z); a0 += w1.x * p.x + w1.y * p.y;
            p = __bfloat1622float2(*(__nv_bfloat162*)&v0.w); a0 += w1.z * p.x + w1.w * p.y;
            p = __bfloat1622float2(*(__nv_bfloat162*)&v1.x); a1 += w0.x * p.x + w0.y * p.y;
            p = __bfloat1622float2(*(__nv_bfloat162*)&v1.y); a1 += w0.z * p.x + w0.w * p.y;
            p = __bfloat1622float2(*(__nv_bfloat162*)&v1.z); a1 += w1.x * p.x + w1.y * p.y;
            p = __bfloat1622float2(*(__nv_bfloat162*)&v1.w); a1 += w1.z * p.x + w1.w * p.y;
        }
        g_gv[b * (LANES_ * CC) + lane * CC + t] = a0;
        g_gv[b * (LANES_ * CC) + lane * CC + t + 32] = a1;
    }
}

// ---------------- K4: conv1x1 + relu + broadcast-add prior ----------------
__global__ void final_kernel(const float* __restrict__ w1x1,
                             const float* __restrict__ b1x1,
                             const float* __restrict__ prior,
                             float* __restrict__ out) {
    int og = blockIdx.x;
    int b = blockIdx.y;
    int tid = threadIdx.x;
    int w = tid >> 5, t = tid & 31;

    __shared__ float gvs[4096];
    __shared__ float vals[8];
    for (int i = tid; i < 4096; i += 256) gvs[i] = g_gv[b * 4096 + i];
    __syncthreads();

    int o = og * 8 + w;
    const float* wrow = w1x1 + (size_t)o * 4096;
    float s = 0.f;
    for (int j = t * 4; j < 4096; j += 128) {
        float4 wv = *(const float4*)&wrow[j];
        float4 gv = *(const float4*)&gvs[j];
        s += wv.x * gv.x + wv.y * gv.y + wv.z * gv.z + wv.w * gv.w;
    }
    #pragma unroll
    for (int off = 16; off > 0; off >>= 1)
        s += __shfl_xor_sync(0xffffffffu, s, off);
    if (t == 0) vals[w] = fmaxf(s + b1x1[o], 0.f);
    __syncthreads();

    for (int i = tid; i < 8 * PE_; i += 256) {
        int oo = i / PE_, e = i % PE_;
        int oabs = og * 8 + oo;
        int idx = b * (CC * PE_) + oabs * PE_ + e;
        out[idx] = vals[oo] + prior[idx];
    }
}

// ---------------- launch ----------------
extern "C" void kernel_launch(void* const* d_in, const int* in_sizes, int n_in,
                              void* d_out, int out_size) {
    const float* feat    = (const float*)d_in[0];
    const float* prior   = (const float*)d_in[1];
    const float* conv_w  = (const float*)d_in[2];
    const float* conv_b  = (const float*)d_in[3];
    const float* fc_w    = (const float*)d_in[4];
    const float* fc_b    = (const float*)d_in[5];
    const float* w1x1    = (const float*)d_in[6];
    const float* b1x1    = (const float*)d_in[7];
    float* out = (float*)d_out;

    const int prep_smem = (FHH * FWW) * 4 + (SPP * LANES_) * 4 + 16;
    const int attn_smem = (CC * RPADH) * 2 + (8 * 260 + 8 * CC) * 4;
    cudaFuncSetAttribute(prep_kernel,
                         cudaFuncAttributeMaxDynamicSharedMemorySize, prep_smem);
    cudaFuncSetAttribute(attn_kernel,
                         cudaFuncAttributeMaxDynamicSharedMemorySize, attn_smem);

    prep_kernel<<<256 + CC * BB, 256, prep_smem>>>(feat, prior, conv_w, conv_b,
                                                   fc_w, fc_b);
    gemm_kernel<<<dim3(32, NSPLIT), 256>>>();
    attn_kernel<<<dim3(8, BB), 256, attn_smem>>>();
    final_kernel<<<dim3(8, BB), 256>>>(w1x1, b1x1, prior, out);
}